// round 14
// baseline (speedup 1.0000x reference)
#include <cuda_runtime.h>
#include <cuda_bf16.h>
#include <cuda_fp16.h>
#include <math.h>
#include <stdint.h>

// Problem constants
#define BB 2
#define NN 2048
#define MM 2048
#define DD 1024
#define HH 16
#define HD 64
#define SCALE 0.125f   // 1/sqrt(64)

#define SROW 20        // smem row stride (floats) for one 16-wide k tile + pad
#define TILEF (128 * SROW)                 // floats per 16-k tile
// stage = 2 k-tiles; 2 stages double-buffered; A and B regions
#define SMEMB (2 * 2 * 2 * TILEF * 4)      // 81920 bytes

// OV kernel geometry (fp16 pipeline)
#define JC 64                               // j-chunk
#define PROW 72                             // P smem row stride (fp16)
#define VROW 72                             // V smem row stride (fp16)
#define OV_PS (128 * PROW)                  // halfs per P buf
#define OV_VS (64 * VROW)                   // halfs per V buf (one of hi/lo)
#define OV_OFF_VSH (2 * OV_PS)
#define OV_OFF_VSL (2 * OV_PS + 2 * OV_VS)
#define OV_SMEMB ((2 * OV_PS + 4 * OV_VS) * 2)   // 73728 bytes

typedef __nv_bfloat16 bf16;
typedef __nv_bfloat162 bf162;

// ---------------------------------------------------------------------------
// Scratch (allocation-free rule: __device__ globals)
// ---------------------------------------------------------------------------
__device__ float  g_Q[(size_t)BB * NN * DD];          // 16 MB
__device__ float  g_K[(size_t)BB * MM * DD];          // 16 MB
__device__ __half g_Vh[(size_t)BB * MM * DD];         // 8 MB (V hi, fp16)
__device__ __half g_Vl[(size_t)BB * MM * DD];         // 8 MB (V lo, fp16)
__device__ float  g_O[(size_t)BB * NN * DD];          // 16 MB
// S fp32 (scores); softmax rewrites each row in place: bytes [0,4096) =
// P fp16[2048], rest of the 8KB row unused.
__device__ float g_S[(size_t)BB * HH * NN * MM];      // 512 MB

// ---------------------------------------------------------------------------
// split helpers
// ---------------------------------------------------------------------------
__device__ __forceinline__ void split_bf16x2(float2 v, uint32_t& hi, uint32_t& lo) {
    bf162 h = __float22bfloat162_rn(v);
    float2 hf = __bfloat1622float2(h);
    bf162 l = __float22bfloat162_rn(make_float2(v.x - hf.x, v.y - hf.y));
    hi = *(uint32_t*)&h;
    lo = *(uint32_t*)&l;
}
__device__ __forceinline__ void split_h2(float2 v, __half2& hi, __half2& lo) {
    hi = __float22half2_rn(v);
    float2 hf = __half22float2(hi);
    lo = __float22half2_rn(make_float2(v.x - hf.x, v.y - hf.y));
}

#define MMA_BF16(d, a0, a1, a2, a3, b0, b1)                                \
    asm volatile("mma.sync.aligned.m16n8k16.row.col.f32.bf16.bf16.f32 "    \
        "{%0,%1,%2,%3}, {%4,%5,%6,%7}, {%8,%9}, {%0,%1,%2,%3};"            \
        : "+f"(d[0]), "+f"(d[1]), "+f"(d[2]), "+f"(d[3])                   \
        : "r"(a0), "r"(a1), "r"(a2), "r"(a3), "r"(b0), "r"(b1))

#define MMA_F16(d, a0, a1, a2, a3, b0, b1)                                 \
    asm volatile("mma.sync.aligned.m16n8k16.row.col.f32.f16.f16.f32 "      \
        "{%0,%1,%2,%3}, {%4,%5,%6,%7}, {%8,%9}, {%0,%1,%2,%3};"            \
        : "+f"(d[0]), "+f"(d[1]), "+f"(d[2]), "+f"(d[3])                   \
        : "r"(a0), "r"(a1), "r"(a2), "r"(a3), "r"(b0), "r"(b1))

__device__ __forceinline__ void cp16(uint32_t dst, const void* src) {
    asm volatile("cp.async.ca.shared.global [%0], [%1], 16;" :: "r"(dst), "l"(src));
}
__device__ __forceinline__ void cp_commit() { asm volatile("cp.async.commit_group;"); }
__device__ __forceinline__ void cp_wait1()  { asm volatile("cp.async.wait_group 1;"); }
__device__ __forceinline__ void cp_wait0()  { asm volatile("cp.async.wait_group 0;"); }

// Load one 128x16 fp32 tile into one smem tile slot.
__device__ __forceinline__ void load_tile16(uint32_t s_base, const float* gsrc,
                                            int ld, int k0, int tid) {
    int r0 = tid >> 2, kc0 = (tid & 3) * 4;
    cp16(s_base + (uint32_t)(r0 * SROW + kc0) * 4, gsrc + (size_t)r0 * ld + k0 + kc0);
    int c1 = tid + 256;
    int r1 = c1 >> 2, kc1 = (c1 & 3) * 4;
    cp16(s_base + (uint32_t)(r1 * SROW + kc1) * 4, gsrc + (size_t)r1 * ld + k0 + kc1);
}

// ---------------------------------------------------------------------------
// Shared 3-term bf16 mainloop, stage = 2 k-tiles (k=32 per barrier pair),
// 2-stage double buffer. acc[mt][nt][4] += Ablk(128xK) * Bblk(128xK)^T
// sa: [2 stages][2 tiles][TILEF] floats; sb likewise. ktiles must be even.
// ---------------------------------------------------------------------------
__device__ __forceinline__ void mma3_mainloop(
    const float* __restrict__ Ab, int lda,
    const float* __restrict__ Bb, int ldb, int ktiles,
    float* sa, float* sb, float (&acc)[4][4][4], int tid)
{
    const int lane = tid & 31;
    const int warp = tid >> 5;
    const int g = lane >> 2, t = lane & 3;
    const int wm0 = (warp >> 2) * 64;
    const int wn0 = (warp & 3) * 32;

    uint32_t sA = (uint32_t)__cvta_generic_to_shared(sa);
    uint32_t sB = (uint32_t)__cvta_generic_to_shared(sb);
    const uint32_t stB = TILEF * 4;

    const int nst = ktiles >> 1;           // stages of 32 k

    // preload stage 0 (tiles 0,1) and stage 1 (tiles 2,3)
    load_tile16(sA + 0 * stB, Ab, lda, 0, tid);
    load_tile16(sA + 1 * stB, Ab, lda, 16, tid);
    load_tile16(sB + 0 * stB, Bb, ldb, 0, tid);
    load_tile16(sB + 1 * stB, Bb, ldb, 16, tid);
    cp_commit();
    if (nst > 1) {
        load_tile16(sA + 2 * stB, Ab, lda, 32, tid);
        load_tile16(sA + 3 * stB, Ab, lda, 48, tid);
        load_tile16(sB + 2 * stB, Bb, ldb, 32, tid);
        load_tile16(sB + 3 * stB, Bb, ldb, 48, tid);
    }
    cp_commit();

    for (int s = 0; s < nst; s++) {
        const int b2 = s & 1;
        if (s + 1 < nst) cp_wait1(); else cp_wait0();
        __syncthreads();

#pragma unroll
        for (int kt2 = 0; kt2 < 2; kt2++) {
            const float* A3 = sa + (b2 * 2 + kt2) * TILEF;
            const float* B3 = sb + (b2 * 2 + kt2) * TILEF;

            uint32_t ah[4][4], al[4][4];
#pragma unroll
            for (int mt = 0; mt < 4; mt++) {
                int rr = wm0 + mt * 16 + g;
                float2 p00 = *(const float2*)&A3[rr * SROW + 2 * t];
                float2 p10 = *(const float2*)&A3[(rr + 8) * SROW + 2 * t];
                float2 p01 = *(const float2*)&A3[rr * SROW + 8 + 2 * t];
                float2 p11 = *(const float2*)&A3[(rr + 8) * SROW + 8 + 2 * t];
                split_bf16x2(p00, ah[mt][0], al[mt][0]);
                split_bf16x2(p10, ah[mt][1], al[mt][1]);
                split_bf16x2(p01, ah[mt][2], al[mt][2]);
                split_bf16x2(p11, ah[mt][3], al[mt][3]);
            }
#pragma unroll
            for (int nt = 0; nt < 4; nt++) {
                int cc = wn0 + nt * 8 + g;
                float2 q0 = *(const float2*)&B3[cc * SROW + 2 * t];
                float2 q1 = *(const float2*)&B3[cc * SROW + 8 + 2 * t];
                uint32_t bh0, bl0, bh1, bl1;
                split_bf16x2(q0, bh0, bl0);
                split_bf16x2(q1, bh1, bl1);
#pragma unroll
                for (int mt = 0; mt < 4; mt++) {
                    float* d = acc[mt][nt];
                    MMA_BF16(d, ah[mt][0], ah[mt][1], ah[mt][2], ah[mt][3], bh0, bh1);
                    MMA_BF16(d, ah[mt][0], ah[mt][1], ah[mt][2], ah[mt][3], bl0, bl1);
                    MMA_BF16(d, al[mt][0], al[mt][1], al[mt][2], al[mt][3], bh0, bh1);
                }
            }
        }
        __syncthreads();

        if (s + 2 < nst) {
            const int k0 = (s + 2) * 32;
            load_tile16(sA + (b2 * 2 + 0) * stB, Ab, lda, k0, tid);
            load_tile16(sA + (b2 * 2 + 1) * stB, Ab, lda, k0 + 16, tid);
            load_tile16(sB + (b2 * 2 + 0) * stB, Bb, ldb, k0, tid);
            load_tile16(sB + (b2 * 2 + 1) * stB, Bb, ldb, k0 + 16, tid);
            cp_commit();
        }
    }
}

// fp32 epilogue: add bias, optional pad-zeroing.
__device__ __forceinline__ void proj_epilogue(
    float (&acc)[4][4][4], const float* __restrict__ bias,
    float* __restrict__ C, const int* __restrict__ pad,
    int m0, int n0, int tid)
{
    const int lane = tid & 31;
    const int warp = tid >> 5;
    const int g = lane >> 2, t = lane & 3;
    const int wm0 = (warp >> 2) * 64;
    const int wn0 = (warp & 3) * 32;

#pragma unroll
    for (int mt = 0; mt < 4; mt++) {
        int r0 = m0 + wm0 + mt * 16 + g;
        int r1 = r0 + 8;
        bool z0 = false, z1 = false;
        if (pad != nullptr) {
            z0 = ((r0 & 2047) >= MM - pad[r0 >> 11]);
            z1 = ((r1 & 2047) >= MM - pad[r1 >> 11]);
        }
#pragma unroll
        for (int nt = 0; nt < 4; nt++) {
            int col = n0 + wn0 + nt * 8 + 2 * t;
            float2 bi = *(const float2*)&bias[col];
            float* d = acc[mt][nt];
            float2 o0 = z0 ? make_float2(0.f, 0.f)
                           : make_float2(d[0] + bi.x, d[1] + bi.y);
            float2 o1 = z1 ? make_float2(0.f, 0.f)
                           : make_float2(d[2] + bi.x, d[3] + bi.y);
            *(float2*)&C[(size_t)r0 * DD + col] = o0;
            *(float2*)&C[(size_t)r1 * DD + col] = o1;
        }
    }
}

// ---------------------------------------------------------------------------
// Fused Q/K/V projection: grid (32, 24). Segment = blockIdx.y >> 3.
// Q, K -> fp32; V -> hi/lo fp16 (OV is the only consumer).
// ---------------------------------------------------------------------------
__global__ __launch_bounds__(256, 2) void qkv_mma(
    const float* __restrict__ q_in, const float* __restrict__ k_in,
    const float* __restrict__ v_in,
    const float* __restrict__ wq, const float* __restrict__ wk,
    const float* __restrict__ wv,
    const float* __restrict__ bq, const float* __restrict__ bk,
    const float* __restrict__ bv,
    const int* __restrict__ kpl)
{
    extern __shared__ float smem[];
    float* sa = smem;
    float* sb = smem + 4 * TILEF;

    const int tid = threadIdx.x;
    const int seg = blockIdx.y >> 3;
    const int n0 = (blockIdx.y & 7) * 128;
    const int m0 = blockIdx.x * 128;

    const float* A    = (seg == 0) ? q_in : (seg == 1) ? k_in : v_in;
    const float* W    = (seg == 0) ? wq   : (seg == 1) ? wk   : wv;
    const float* bias = (seg == 0) ? bq   : (seg == 1) ? bk   : bv;

    float acc[4][4][4];
#pragma unroll
    for (int i = 0; i < 4; i++)
#pragma unroll
        for (int j = 0; j < 4; j++)
#pragma unroll
            for (int p = 0; p < 4; p++) acc[i][j][p] = 0.f;

    mma3_mainloop(A + (size_t)m0 * DD, DD, W + (size_t)n0 * DD, DD,
                  64, sa, sb, acc, tid);

    if (seg == 2) {
        const int lane = tid & 31;
        const int warp = tid >> 5;
        const int g = lane >> 2, t = lane & 3;
        const int wm0 = (warp >> 2) * 64;
        const int wn0 = (warp & 3) * 32;
#pragma unroll
        for (int mt = 0; mt < 4; mt++) {
            int r0 = m0 + wm0 + mt * 16 + g;
            int r1 = r0 + 8;
#pragma unroll
            for (int nt = 0; nt < 4; nt++) {
                int col = n0 + wn0 + nt * 8 + 2 * t;
                float2 bi = *(const float2*)&bias[col];
                float* d = acc[mt][nt];
                __half2 h0, l0, h1, l1;
                split_h2(make_float2(d[0] + bi.x, d[1] + bi.y), h0, l0);
                split_h2(make_float2(d[2] + bi.x, d[3] + bi.y), h1, l1);
                *(__half2*)&g_Vh[(size_t)r0 * DD + col] = h0;
                *(__half2*)&g_Vl[(size_t)r0 * DD + col] = l0;
                *(__half2*)&g_Vh[(size_t)r1 * DD + col] = h1;
                *(__half2*)&g_Vl[(size_t)r1 * DD + col] = l1;
            }
        }
    } else {
        float* C = (seg == 0) ? g_Q : g_K;
        const int* pad = (seg == 1) ? kpl : nullptr;
        proj_epilogue(acc, bias, C, pad, m0, n0, tid);
    }
}

// ---------------------------------------------------------------------------
// Output projection: C = A @ W^T + bias. Grid (32, 8).
// ---------------------------------------------------------------------------
__global__ __launch_bounds__(256, 2) void proj_mma(
    const float* __restrict__ A, const float* __restrict__ W,
    const float* __restrict__ bias, float* __restrict__ C)
{
    extern __shared__ float smem[];
    float* sa = smem;
    float* sb = smem + 4 * TILEF;

    const int tid = threadIdx.x;
    const int m0 = blockIdx.x * 128;
    const int n0 = blockIdx.y * 128;

    float acc[4][4][4];
#pragma unroll
    for (int i = 0; i < 4; i++)
#pragma unroll
        for (int j = 0; j < 4; j++)
#pragma unroll
            for (int p = 0; p < 4; p++) acc[i][j][p] = 0.f;

    mma3_mainloop(A + (size_t)m0 * DD, DD, W + (size_t)n0 * DD, DD,
                  64, sa, sb, acc, tid);
    proj_epilogue(acc, bias, C, nullptr, m0, n0, tid);
}

// ---------------------------------------------------------------------------
// Scores: S[bh,n,m] = (Q·K) * SCALE, 128x128 tiles, K=64. Causal skip.
// ---------------------------------------------------------------------------
__global__ __launch_bounds__(256, 2) void scores_mma(const int* __restrict__ flag)
{
    const int mt = blockIdx.x, ntb = blockIdx.y, bh = blockIdx.z;
    if (flag[0] != 0 && mt > ntb) return;

    extern __shared__ float smem[];
    float* sa = smem;
    float* sb = smem + 4 * TILEF;

    const int b = bh >> 4, h = bh & 15;
    const int n0 = ntb * 128, m0 = mt * 128;
    const int tid = threadIdx.x;

    float acc[4][4][4];
#pragma unroll
    for (int i = 0; i < 4; i++)
#pragma unroll
        for (int j = 0; j < 4; j++)
#pragma unroll
            for (int p = 0; p < 4; p++) acc[i][j][p] = 0.f;

    const float* Ab = g_Q + (size_t)b * NN * DD + (size_t)n0 * DD + h * HD;
    const float* Bb = g_K + (size_t)b * MM * DD + (size_t)m0 * DD + h * HD;

    mma3_mainloop(Ab, DD, Bb, DD, 4, sa, sb, acc, tid);

    const int lane = tid & 31;
    const int warp = tid >> 5;
    const int g = lane >> 2, t = lane & 3;
    const int wm0 = (warp >> 2) * 64;
    const int wn0 = (warp & 3) * 32;

    float* Sbase = g_S + (size_t)bh * NN * MM;
#pragma unroll
    for (int qt = 0; qt < 4; qt++) {
        int r0 = n0 + wm0 + qt * 16 + g;
        int r1 = r0 + 8;
#pragma unroll
        for (int kt = 0; kt < 4; kt++) {
            int col = m0 + wn0 + kt * 8 + 2 * t;
            float* d = acc[qt][kt];
            *(float2*)&Sbase[(size_t)r0 * MM + col] =
                make_float2(d[0] * SCALE, d[1] * SCALE);
            *(float2*)&Sbase[(size_t)r1 * MM + col] =
                make_float2(d[2] * SCALE, d[3] * SCALE);
        }
    }
}

// ---------------------------------------------------------------------------
// Fused softmax + head-mean, heavy rows first. Rewrites each P row IN PLACE
// as fp16[2048] in the row's first 4KB; zero-padded to 128-boundary.
// wmean accumulated in fp32 BEFORE the fp16 conversion (exact).
// ---------------------------------------------------------------------------
__global__ __launch_bounds__(256) void softmax_wmean(const int* __restrict__ flag,
                                                     float* __restrict__ wout)
{
    const int blk = blockIdx.x;
    const int b = blk >> 11;
    const int n = NN - 1 - (blk & (NN - 1));
    const int causal = (flag[0] != 0);
    const int len    = causal ? (n + 1) : MM;
    const int lenpad = causal ? min((((n >> 7) + 1) << 7), MM) : MM;
    const int tid = threadIdx.x;
    const float NEGINF = __int_as_float(0xff800000);

    __shared__ float red[8];
    float2 wacc[4];
#pragma unroll
    for (int k = 0; k < 4; k++) wacc[k] = make_float2(0.f, 0.f);

    for (int h = 0; h < HH; h++) {
        float* row = g_S + (((size_t)(b * HH + h) * NN) + n) * MM;

        float2 v2[4];
        float mx = NEGINF;
#pragma unroll
        for (int k = 0; k < 4; k++) {
            int j2 = tid * 2 + k * 512;
            float2 s = *(const float2*)&row[j2];
            s.x = (j2     < len) ? s.x : NEGINF;
            s.y = (j2 + 1 < len) ? s.y : NEGINF;
            v2[k] = s;
            mx = fmaxf(mx, fmaxf(s.x, s.y));
        }
#pragma unroll
        for (int o = 16; o > 0; o >>= 1)
            mx = fmaxf(mx, __shfl_xor_sync(0xffffffffu, mx, o));
        if ((tid & 31) == 0) red[tid >> 5] = mx;
        __syncthreads();
        float bm = red[0];
#pragma unroll
        for (int w = 1; w < 8; w++) bm = fmaxf(bm, red[w]);
        __syncthreads();

        float sum = 0.f;
#pragma unroll
        for (int k = 0; k < 4; k++) {
            v2[k].x = expf(v2[k].x - bm);
            v2[k].y = expf(v2[k].y - bm);
            sum += v2[k].x + v2[k].y;
        }
#pragma unroll
        for (int o = 16; o > 0; o >>= 1)
            sum += __shfl_xor_sync(0xffffffffu, sum, o);
        if ((tid & 31) == 0) red[tid >> 5] = sum;
        __syncthreads();
        float tot = red[0];
#pragma unroll
        for (int w = 1; w < 8; w++) tot += red[w];
        __syncthreads();
        float inv = 1.0f / tot;

        uint32_t* rowW = (uint32_t*)row;
#pragma unroll
        for (int k = 0; k < 4; k++) {
            int j2 = tid * 2 + k * 512;
            float2 p = make_float2(v2[k].x * inv, v2[k].y * inv);
            wacc[k].x += p.x;
            wacc[k].y += p.y;
            if (j2 < lenpad) {
                __half2 ph = __float22half2_rn(p);
                rowW[j2 >> 1] = *(uint32_t*)&ph;
            }
        }
    }

    if (wout != nullptr) {
        float* orow = wout + ((size_t)b * NN + n) * MM;
#pragma unroll
        for (int k = 0; k < 4; k++) {
            int j2 = tid * 2 + k * 512;
            *(float2*)&orow[j2] = make_float2(wacc[k].x * (1.0f / HH),
                                              wacc[k].y * (1.0f / HH));
        }
    }
}

// ---------------------------------------------------------------------------
// OV on tensor cores: P fp16 single x V fp16 hi/lo, 2 MMA terms.
// j-chunk 64, double-buffered, heavy blocks first, 3 CTAs/SM.
// ---------------------------------------------------------------------------
__global__ __launch_bounds__(256, 3) void attn_ov(const int* __restrict__ flag)
{
    const int ntb = gridDim.x - 1 - blockIdx.x;   // heavy first
    const int bh = blockIdx.y;
    const int b = bh >> 4, h = bh & 15;
    const int n0 = ntb * 128;
    const int chunks = (flag[0] != 0) ? ((n0 + 128) / JC) : (MM / JC);

    extern __shared__ __half ovs[];
    uint32_t s0 = (uint32_t)__cvta_generic_to_shared(ovs);

    const int tid = threadIdx.x;
    const int lane = tid & 31, warp = tid >> 5;
    const int g = lane >> 2, t = lane & 3;
    const int wy = warp >> 1;            // n-dir 0..3
    const int wx = warp & 1;             // d-dir 0..1

    const char* Pbytes = (const char*)(g_S + ((size_t)bh * NN + n0) * MM);
    const __half* VbH = g_Vh + (size_t)b * MM * DD + h * HD;
    const __half* VbL = g_Vl + (size_t)b * MM * DD + h * HD;

    float acc[2][4][4];
#pragma unroll
    for (int i = 0; i < 2; i++)
#pragma unroll
        for (int j = 0; j < 4; j++)
#pragma unroll
            for (int p = 0; p < 4; p++) acc[i][j][p] = 0.f;

    auto load_chunk = [&](int c, int buf) {
        const int j0 = c * JC;
#pragma unroll
        for (int i = 0; i < 4; i++) {
            int idx = tid + i * 256;            // 0..1023
            int r = idx >> 3, seg = idx & 7;    // row, 16B segment
            const char* psrc = Pbytes + (size_t)r * (MM * 4) + j0 * 2 + seg * 16;
            uint32_t d = (uint32_t)(buf * OV_PS + r * PROW) * 2 + seg * 16;
            cp16(s0 + d, psrc);
        }
#pragma unroll
        for (int i = 0; i < 2; i++) {
            int idx = tid + i * 256;            // 0..511
            int r = idx >> 3, seg = idx & 7;
            size_t voff = (size_t)(j0 + r) * DD + seg * 8;
            uint32_t d = (uint32_t)(buf * OV_VS + r * VROW) * 2 + seg * 16;
            cp16(s0 + OV_OFF_VSH * 2 + d, VbH + voff);
            cp16(s0 + OV_OFF_VSL * 2 + d, VbL + voff);
        }
    };

    load_chunk(0, 0);
    cp_commit();

    for (int c = 0; c < chunks; c++) {
        const int buf = c & 1;
        if (c + 1 < chunks) {
            load_chunk(c + 1, buf ^ 1);
            cp_commit();
            cp_wait1();
        } else {
            cp_wait0();
        }
        __syncthreads();

        const __half* PP = ovs + buf * OV_PS;
        const __half* VH = ovs + OV_OFF_VSH + buf * OV_VS;
        const __half* VL = ovs + OV_OFF_VSL + buf * OV_VS;

#pragma unroll
        for (int ks = 0; ks < 4; ks++) {
            const int jb = ks * 16;
            uint32_t ap[2][4];
#pragma unroll
            for (int mt = 0; mt < 2; mt++) {
                int rr = wy * 32 + mt * 16 + g;
                ap[mt][0] = *(const uint32_t*)&PP[rr * PROW + jb + 2 * t];
                ap[mt][1] = *(const uint32_t*)&PP[(rr + 8) * PROW + jb + 2 * t];
                ap[mt][2] = *(const uint32_t*)&PP[rr * PROW + jb + 8 + 2 * t];
                ap[mt][3] = *(const uint32_t*)&PP[(rr + 8) * PROW + jb + 8 + 2 * t];
            }
#pragma unroll
            for (int nt = 0; nt < 4; nt++) {
                int dd = wx * 32 + nt * 8 + g;
                uint32_t bh0 = (uint32_t)*(const unsigned short*)&VH[(jb + 2 * t) * VROW + dd]
                             | ((uint32_t)*(const unsigned short*)&VH[(jb + 2 * t + 1) * VROW + dd] << 16);
                uint32_t bh1 = (uint32_t)*(const unsigned short*)&VH[(jb + 8 + 2 * t) * VROW + dd]
                             | ((uint32_t)*(const unsigned short*)&VH[(jb + 9 + 2 * t) * VROW + dd] << 16);
                uint32_t bl0 = (uint32_t)*(const unsigned short*)&VL[(jb + 2 * t) * VROW + dd]
                             | ((uint32_t)*(const unsigned short*)&VL[(jb + 2 * t + 1) * VROW + dd] << 16);
                uint32_t bl1 = (uint32_t)*(const unsigned short*)&VL[(jb + 8 + 2 * t) * VROW + dd]
                             | ((uint32_t)*(const unsigned short*)&VL[(jb + 9 + 2 * t) * VROW + dd] << 16);
#pragma unroll
                for (int mt = 0; mt < 2; mt++) {
                    float* d = acc[mt][nt];
                    MMA_F16(d, ap[mt][0], ap[mt][1], ap[mt][2], ap[mt][3], bh0, bh1);
                    MMA_F16(d, ap[mt][0], ap[mt][1], ap[mt][2], ap[mt][3], bl0, bl1);
                }
            }
        }
        __syncthreads();
    }

#pragma unroll
    for (int mt = 0; mt < 2; mt++) {
        int r0 = n0 + wy * 32 + mt * 16 + g;
        int r1 = r0 + 8;
#pragma unroll
        for (int nt = 0; nt < 4; nt++) {
            int col = h * HD + wx * 32 + nt * 8 + 2 * t;
            float* d = acc[mt][nt];
            *(float2*)&g_O[((size_t)b * NN + r0) * DD + col] = make_float2(d[0], d[1]);
            *(float2*)&g_O[((size_t)b * NN + r1) * DD + col] = make_float2(d[2], d[3]);
        }
    }
}

// ---------------------------------------------------------------------------
// Launch
// ---------------------------------------------------------------------------
extern "C" void kernel_launch(void* const* d_in, const int* in_sizes, int n_in,
                              void* d_out, int out_size)
{
    const float* query = (const float*)d_in[0];
    const float* key   = (const float*)d_in[1];
    const float* value = (const float*)d_in[2];
    const int*   kpl   = (const int*)d_in[3];
    const int*   flag  = (const int*)d_in[4];
    const float* wq_w  = (const float*)d_in[5];
    const float* wq_b  = (const float*)d_in[6];
    const float* wk_w  = (const float*)d_in[7];
    const float* wk_b  = (const float*)d_in[8];
    const float* wv_w  = (const float*)d_in[9];
    const float* wv_b  = (const float*)d_in[10];
    const float* wo_w  = (const float*)d_in[11];
    const float* wo_b  = (const float*)d_in[12];
    float* out = (float*)d_out;

    static bool attr_done = false;
    if (!attr_done) {
        cudaFuncSetAttribute(qkv_mma,    cudaFuncAttributeMaxDynamicSharedMemorySize, SMEMB);
        cudaFuncSetAttribute(proj_mma,   cudaFuncAttributeMaxDynamicSharedMemorySize, SMEMB);
        cudaFuncSetAttribute(scores_mma, cudaFuncAttributeMaxDynamicSharedMemorySize, SMEMB);
        cudaFuncSetAttribute(attn_ov,    cudaFuncAttributeMaxDynamicSharedMemorySize, OV_SMEMB);
        attr_done = true;
    }

    float *Op;
    cudaGetSymbolAddress((void**)&Op, g_O);

    qkv_mma<<<dim3(32, 24), 256, SMEMB>>>(query, key, value,
                                          wq_w, wk_w, wv_w,
                                          wq_b, wk_b, wv_b, kpl);

    scores_mma<<<dim3(16, 16, 32), 256, SMEMB>>>(flag);

    const long long need = (long long)BB * NN * DD + (long long)BB * NN * MM;
    float* wout = ((long long)out_size >= need) ? (out + (size_t)BB * NN * DD)
                                                : nullptr;
    softmax_wmean<<<BB * NN, 256>>>(flag, wout);

    attn_ov<<<dim3(16, 32), 256, OV_SMEMB>>>(flag);

    proj_mma<<<dim3(32, 8), 256, SMEMB>>>(Op, wo_w, wo_b, out);
}

// round 15
// speedup vs baseline: 1.1879x; 1.1879x over previous
#include <cuda_runtime.h>
#include <cuda_bf16.h>
#include <cuda_fp16.h>
#include <math.h>
#include <stdint.h>

// Problem constants
#define BB 2
#define NN 2048
#define MM 2048
#define DD 1024
#define HH 16
#define HD 64
#define SCALE 0.125f   // 1/sqrt(64)

#define SROW 20        // smem row stride (floats) for 16-wide k tile + pad
#define STAGES 3
#define TILEF (128 * SROW)                 // floats per tile-stage
#define SMEMB (STAGES * 2 * TILEF * 4)     // dynamic smem bytes (61440)

// OV kernel geometry (fp16 pipeline, single-V)
#define JC 64                               // j-chunk
#define PROW 72                             // P smem row stride (fp16)
#define VROW 72                             // V smem row stride (fp16)
#define OV_PS (128 * PROW)                  // halfs per P buf
#define OV_VS (64 * VROW)                   // halfs per V buf
#define OV_OFF_VS (2 * OV_PS)
#define OV_SMEMB ((2 * OV_PS + 2 * OV_VS) * 2)   // 55296 bytes

typedef __nv_bfloat16 bf16;
typedef __nv_bfloat162 bf162;

// ---------------------------------------------------------------------------
// Scratch (allocation-free rule: __device__ globals)
// ---------------------------------------------------------------------------
__device__ float  g_Q[(size_t)BB * NN * DD];          // 16 MB
__device__ float  g_K[(size_t)BB * MM * DD];          // 16 MB
__device__ __half g_V16[(size_t)BB * MM * DD];        // 8 MB (V, single fp16)
__device__ float  g_O[(size_t)BB * NN * DD];          // 16 MB
// S fp32 (scores); softmax rewrites each row in place: bytes [0,4096) =
// P fp16[2048], rest of the 8KB row unused.
__device__ float g_S[(size_t)BB * HH * NN * MM];      // 512 MB

// ---------------------------------------------------------------------------
// split helpers
// ---------------------------------------------------------------------------
__device__ __forceinline__ void split_bf16x2(float2 v, uint32_t& hi, uint32_t& lo) {
    bf162 h = __float22bfloat162_rn(v);
    float2 hf = __bfloat1622float2(h);
    bf162 l = __float22bfloat162_rn(make_float2(v.x - hf.x, v.y - hf.y));
    hi = *(uint32_t*)&h;
    lo = *(uint32_t*)&l;
}

#define MMA_BF16(d, a0, a1, a2, a3, b0, b1)                                \
    asm volatile("mma.sync.aligned.m16n8k16.row.col.f32.bf16.bf16.f32 "    \
        "{%0,%1,%2,%3}, {%4,%5,%6,%7}, {%8,%9}, {%0,%1,%2,%3};"            \
        : "+f"(d[0]), "+f"(d[1]), "+f"(d[2]), "+f"(d[3])                   \
        : "r"(a0), "r"(a1), "r"(a2), "r"(a3), "r"(b0), "r"(b1))

#define MMA_F16(d, a0, a1, a2, a3, b0, b1)                                 \
    asm volatile("mma.sync.aligned.m16n8k16.row.col.f32.f16.f16.f32 "      \
        "{%0,%1,%2,%3}, {%4,%5,%6,%7}, {%8,%9}, {%0,%1,%2,%3};"            \
        : "+f"(d[0]), "+f"(d[1]), "+f"(d[2]), "+f"(d[3])                   \
        : "r"(a0), "r"(a1), "r"(a2), "r"(a3), "r"(b0), "r"(b1))

__device__ __forceinline__ void cp16(uint32_t dst, const void* src) {
    asm volatile("cp.async.ca.shared.global [%0], [%1], 16;" :: "r"(dst), "l"(src));
}
__device__ __forceinline__ void cp_commit() { asm volatile("cp.async.commit_group;"); }
__device__ __forceinline__ void cp_wait2()  { asm volatile("cp.async.wait_group 2;"); }
__device__ __forceinline__ void cp_wait1()  { asm volatile("cp.async.wait_group 1;"); }
__device__ __forceinline__ void cp_wait0()  { asm volatile("cp.async.wait_group 0;"); }

// Load one 128x16 fp32 tile into one smem stage.
__device__ __forceinline__ void load_tile16(uint32_t s_base, const float* gsrc,
                                            int ld, int k0, int tid) {
    int r0 = tid >> 2, kc0 = (tid & 3) * 4;
    cp16(s_base + (uint32_t)(r0 * SROW + kc0) * 4, gsrc + (size_t)r0 * ld + k0 + kc0);
    int c1 = tid + 256;
    int r1 = c1 >> 2, kc1 = (c1 & 3) * 4;
    cp16(s_base + (uint32_t)(r1 * SROW + kc1) * 4, gsrc + (size_t)r1 * ld + k0 + kc1);
}

// ---------------------------------------------------------------------------
// Shared 3-term bf16 mainloop (R13's proven 3-stage cp.async pipeline).
// acc[mt][nt][4] += Ablk(128xK) * Bblk(128xK)^T
// ---------------------------------------------------------------------------
__device__ __forceinline__ void mma3_mainloop(
    const float* __restrict__ Ab, int lda,
    const float* __restrict__ Bb, int ldb, int ktiles,
    float* sa, float* sb, float (&acc)[4][4][4], int tid)
{
    const int lane = tid & 31;
    const int warp = tid >> 5;
    const int g = lane >> 2, t = lane & 3;
    const int wm0 = (warp >> 2) * 64;
    const int wn0 = (warp & 3) * 32;

    uint32_t sA = (uint32_t)__cvta_generic_to_shared(sa);
    uint32_t sB = (uint32_t)__cvta_generic_to_shared(sb);
    const uint32_t stB = TILEF * 4;

    load_tile16(sA, Ab, lda, 0, tid);
    load_tile16(sB, Bb, ldb, 0, tid);
    cp_commit();
    if (ktiles > 1) {
        load_tile16(sA + stB, Ab, lda, 16, tid);
        load_tile16(sB + stB, Bb, ldb, 16, tid);
    }
    cp_commit();

    for (int c = 0; c < ktiles; c++) {
        const int buf = c % 3;
        if (c + 2 < ktiles) {
            uint32_t off = ((c + 2) % 3) * stB;
            load_tile16(sA + off, Ab, lda, (c + 2) * 16, tid);
            load_tile16(sB + off, Bb, ldb, (c + 2) * 16, tid);
            cp_commit();
            cp_wait2();
        } else if (c + 1 < ktiles) {
            cp_wait1();
        } else {
            cp_wait0();
        }
        __syncthreads();

        const float* A3 = sa + buf * TILEF;
        const float* B3 = sb + buf * TILEF;

        uint32_t ah[4][4], al[4][4];
#pragma unroll
        for (int mt = 0; mt < 4; mt++) {
            int rr = wm0 + mt * 16 + g;
            float2 p00 = *(const float2*)&A3[rr * SROW + 2 * t];
            float2 p10 = *(const float2*)&A3[(rr + 8) * SROW + 2 * t];
            float2 p01 = *(const float2*)&A3[rr * SROW + 8 + 2 * t];
            float2 p11 = *(const float2*)&A3[(rr + 8) * SROW + 8 + 2 * t];
            split_bf16x2(p00, ah[mt][0], al[mt][0]);
            split_bf16x2(p10, ah[mt][1], al[mt][1]);
            split_bf16x2(p01, ah[mt][2], al[mt][2]);
            split_bf16x2(p11, ah[mt][3], al[mt][3]);
        }
#pragma unroll
        for (int nt = 0; nt < 4; nt++) {
            int cc = wn0 + nt * 8 + g;
            float2 q0 = *(const float2*)&B3[cc * SROW + 2 * t];
            float2 q1 = *(const float2*)&B3[cc * SROW + 8 + 2 * t];
            uint32_t bh0, bl0, bh1, bl1;
            split_bf16x2(q0, bh0, bl0);
            split_bf16x2(q1, bh1, bl1);
#pragma unroll
            for (int mt = 0; mt < 4; mt++) {
                float* d = acc[mt][nt];
                MMA_BF16(d, ah[mt][0], ah[mt][1], ah[mt][2], ah[mt][3], bh0, bh1);
                MMA_BF16(d, ah[mt][0], ah[mt][1], ah[mt][2], ah[mt][3], bl0, bl1);
                MMA_BF16(d, al[mt][0], al[mt][1], al[mt][2], al[mt][3], bh0, bh1);
            }
        }
        __syncthreads();
    }
}

// fp32 epilogue: add bias, optional pad-zeroing.
__device__ __forceinline__ void proj_epilogue(
    float (&acc)[4][4][4], const float* __restrict__ bias,
    float* __restrict__ C, const int* __restrict__ pad,
    int m0, int n0, int tid)
{
    const int lane = tid & 31;
    const int warp = tid >> 5;
    const int g = lane >> 2, t = lane & 3;
    const int wm0 = (warp >> 2) * 64;
    const int wn0 = (warp & 3) * 32;

#pragma unroll
    for (int mt = 0; mt < 4; mt++) {
        int r0 = m0 + wm0 + mt * 16 + g;
        int r1 = r0 + 8;
        bool z0 = false, z1 = false;
        if (pad != nullptr) {
            z0 = ((r0 & 2047) >= MM - pad[r0 >> 11]);
            z1 = ((r1 & 2047) >= MM - pad[r1 >> 11]);
        }
#pragma unroll
        for (int nt = 0; nt < 4; nt++) {
            int col = n0 + wn0 + nt * 8 + 2 * t;
            float2 bi = *(const float2*)&bias[col];
            float* d = acc[mt][nt];
            float2 o0 = z0 ? make_float2(0.f, 0.f)
                           : make_float2(d[0] + bi.x, d[1] + bi.y);
            float2 o1 = z1 ? make_float2(0.f, 0.f)
                           : make_float2(d[2] + bi.x, d[3] + bi.y);
            *(float2*)&C[(size_t)r0 * DD + col] = o0;
            *(float2*)&C[(size_t)r1 * DD + col] = o1;
        }
    }
}

// ---------------------------------------------------------------------------
// Fused Q/K/V projection: grid (32, 24). Segment = blockIdx.y >> 3.
// Q, K -> fp32; V -> single fp16.
// ---------------------------------------------------------------------------
__global__ __launch_bounds__(256, 2) void qkv_mma(
    const float* __restrict__ q_in, const float* __restrict__ k_in,
    const float* __restrict__ v_in,
    const float* __restrict__ wq, const float* __restrict__ wk,
    const float* __restrict__ wv,
    const float* __restrict__ bq, const float* __restrict__ bk,
    const float* __restrict__ bv,
    const int* __restrict__ kpl)
{
    extern __shared__ float smem[];
    float* sa = smem;
    float* sb = smem + STAGES * TILEF;

    const int tid = threadIdx.x;
    const int seg = blockIdx.y >> 3;
    const int n0 = (blockIdx.y & 7) * 128;
    const int m0 = blockIdx.x * 128;

    const float* A    = (seg == 0) ? q_in : (seg == 1) ? k_in : v_in;
    const float* W    = (seg == 0) ? wq   : (seg == 1) ? wk   : wv;
    const float* bias = (seg == 0) ? bq   : (seg == 1) ? bk   : bv;

    float acc[4][4][4];
#pragma unroll
    for (int i = 0; i < 4; i++)
#pragma unroll
        for (int j = 0; j < 4; j++)
#pragma unroll
            for (int p = 0; p < 4; p++) acc[i][j][p] = 0.f;

    mma3_mainloop(A + (size_t)m0 * DD, DD, W + (size_t)n0 * DD, DD,
                  64, sa, sb, acc, tid);

    if (seg == 2) {
        const int lane = tid & 31;
        const int warp = tid >> 5;
        const int g = lane >> 2, t = lane & 3;
        const int wm0 = (warp >> 2) * 64;
        const int wn0 = (warp & 3) * 32;
#pragma unroll
        for (int mt = 0; mt < 4; mt++) {
            int r0 = m0 + wm0 + mt * 16 + g;
            int r1 = r0 + 8;
#pragma unroll
            for (int nt = 0; nt < 4; nt++) {
                int col = n0 + wn0 + nt * 8 + 2 * t;
                float2 bi = *(const float2*)&bias[col];
                float* d = acc[mt][nt];
                __half2 h0 = __float22half2_rn(make_float2(d[0] + bi.x, d[1] + bi.y));
                __half2 h1 = __float22half2_rn(make_float2(d[2] + bi.x, d[3] + bi.y));
                *(__half2*)&g_V16[(size_t)r0 * DD + col] = h0;
                *(__half2*)&g_V16[(size_t)r1 * DD + col] = h1;
            }
        }
    } else {
        float* C = (seg == 0) ? g_Q : g_K;
        const int* pad = (seg == 1) ? kpl : nullptr;
        proj_epilogue(acc, bias, C, pad, m0, n0, tid);
    }
}

// ---------------------------------------------------------------------------
// Output projection: C = A @ W^T + bias. Grid (32, 8).
// ---------------------------------------------------------------------------
__global__ __launch_bounds__(256, 2) void proj_mma(
    const float* __restrict__ A, const float* __restrict__ W,
    const float* __restrict__ bias, float* __restrict__ C)
{
    extern __shared__ float smem[];
    float* sa = smem;
    float* sb = smem + STAGES * TILEF;

    const int tid = threadIdx.x;
    const int m0 = blockIdx.x * 128;
    const int n0 = blockIdx.y * 128;

    float acc[4][4][4];
#pragma unroll
    for (int i = 0; i < 4; i++)
#pragma unroll
        for (int j = 0; j < 4; j++)
#pragma unroll
            for (int p = 0; p < 4; p++) acc[i][j][p] = 0.f;

    mma3_mainloop(A + (size_t)m0 * DD, DD, W + (size_t)n0 * DD, DD,
                  64, sa, sb, acc, tid);
    proj_epilogue(acc, bias, C, nullptr, m0, n0, tid);
}

// ---------------------------------------------------------------------------
// Scores: S[bh,n,m] = (Q·K) * SCALE, 128x128 tiles, K=64. Causal skip.
// ---------------------------------------------------------------------------
__global__ __launch_bounds__(256, 2) void scores_mma(const int* __restrict__ flag)
{
    const int mt = blockIdx.x, ntb = blockIdx.y, bh = blockIdx.z;
    if (flag[0] != 0 && mt > ntb) return;

    extern __shared__ float smem[];
    float* sa = smem;
    float* sb = smem + STAGES * TILEF;

    const int b = bh >> 4, h = bh & 15;
    const int n0 = ntb * 128, m0 = mt * 128;
    const int tid = threadIdx.x;

    float acc[4][4][4];
#pragma unroll
    for (int i = 0; i < 4; i++)
#pragma unroll
        for (int j = 0; j < 4; j++)
#pragma unroll
            for (int p = 0; p < 4; p++) acc[i][j][p] = 0.f;

    const float* Ab = g_Q + (size_t)b * NN * DD + (size_t)n0 * DD + h * HD;
    const float* Bb = g_K + (size_t)b * MM * DD + (size_t)m0 * DD + h * HD;

    mma3_mainloop(Ab, DD, Bb, DD, 4, sa, sb, acc, tid);

    const int lane = tid & 31;
    const int warp = tid >> 5;
    const int g = lane >> 2, t = lane & 3;
    const int wm0 = (warp >> 2) * 64;
    const int wn0 = (warp & 3) * 32;

    float* Sbase = g_S + (size_t)bh * NN * MM;
#pragma unroll
    for (int qt = 0; qt < 4; qt++) {
        int r0 = n0 + wm0 + qt * 16 + g;
        int r1 = r0 + 8;
#pragma unroll
        for (int kt = 0; kt < 4; kt++) {
            int col = m0 + wn0 + kt * 8 + 2 * t;
            float* d = acc[qt][kt];
            *(float2*)&Sbase[(size_t)r0 * MM + col] =
                make_float2(d[0] * SCALE, d[1] * SCALE);
            *(float2*)&Sbase[(size_t)r1 * MM + col] =
                make_float2(d[2] * SCALE, d[3] * SCALE);
        }
    }
}

// ---------------------------------------------------------------------------
// Fused softmax + head-mean, heavy rows first. Rewrites each P row IN PLACE
// as fp16[2048] in the row's first 4KB; zero-padded to 128-boundary.
// wmean accumulated in fp32 BEFORE the fp16 conversion (exact).
// ---------------------------------------------------------------------------
__global__ __launch_bounds__(256) void softmax_wmean(const int* __restrict__ flag,
                                                     float* __restrict__ wout)
{
    const int blk = blockIdx.x;
    const int b = blk >> 11;
    const int n = NN - 1 - (blk & (NN - 1));
    const int causal = (flag[0] != 0);
    const int len    = causal ? (n + 1) : MM;
    const int lenpad = causal ? min((((n >> 7) + 1) << 7), MM) : MM;
    const int tid = threadIdx.x;
    const float NEGINF = __int_as_float(0xff800000);

    __shared__ float red[8];
    float2 wacc[4];
#pragma unroll
    for (int k = 0; k < 4; k++) wacc[k] = make_float2(0.f, 0.f);

    for (int h = 0; h < HH; h++) {
        float* row = g_S + (((size_t)(b * HH + h) * NN) + n) * MM;

        float2 v2[4];
        float mx = NEGINF;
#pragma unroll
        for (int k = 0; k < 4; k++) {
            int j2 = tid * 2 + k * 512;
            float2 s = *(const float2*)&row[j2];
            s.x = (j2     < len) ? s.x : NEGINF;
            s.y = (j2 + 1 < len) ? s.y : NEGINF;
            v2[k] = s;
            mx = fmaxf(mx, fmaxf(s.x, s.y));
        }
#pragma unroll
        for (int o = 16; o > 0; o >>= 1)
            mx = fmaxf(mx, __shfl_xor_sync(0xffffffffu, mx, o));
        if ((tid & 31) == 0) red[tid >> 5] = mx;
        __syncthreads();
        float bm = red[0];
#pragma unroll
        for (int w = 1; w < 8; w++) bm = fmaxf(bm, red[w]);
        __syncthreads();

        float sum = 0.f;
#pragma unroll
        for (int k = 0; k < 4; k++) {
            v2[k].x = expf(v2[k].x - bm);
            v2[k].y = expf(v2[k].y - bm);
            sum += v2[k].x + v2[k].y;
        }
#pragma unroll
        for (int o = 16; o > 0; o >>= 1)
            sum += __shfl_xor_sync(0xffffffffu, sum, o);
        if ((tid & 31) == 0) red[tid >> 5] = sum;
        __syncthreads();
        float tot = red[0];
#pragma unroll
        for (int w = 1; w < 8; w++) tot += red[w];
        __syncthreads();
        float inv = 1.0f / tot;

        uint32_t* rowW = (uint32_t*)row;
#pragma unroll
        for (int k = 0; k < 4; k++) {
            int j2 = tid * 2 + k * 512;
            float2 p = make_float2(v2[k].x * inv, v2[k].y * inv);
            wacc[k].x += p.x;
            wacc[k].y += p.y;
            if (j2 < lenpad) {
                __half2 ph = __float22half2_rn(p);
                rowW[j2 >> 1] = *(uint32_t*)&ph;
            }
        }
    }

    if (wout != nullptr) {
        float* orow = wout + ((size_t)b * NN + n) * MM;
#pragma unroll
        for (int k = 0; k < 4; k++) {
            int j2 = tid * 2 + k * 512;
            *(float2*)&orow[j2] = make_float2(wacc[k].x * (1.0f / HH),
                                              wacc[k].y * (1.0f / HH));
        }
    }
}

// ---------------------------------------------------------------------------
// OV on tensor cores: P fp16 x V fp16, single MMA term.
// j-chunk 64, double-buffered, heavy blocks first, 3 CTAs/SM.
// ---------------------------------------------------------------------------
__global__ __launch_bounds__(256, 3) void attn_ov(const int* __restrict__ flag)
{
    const int ntb = gridDim.x - 1 - blockIdx.x;   // heavy first
    const int bh = blockIdx.y;
    const int b = bh >> 4, h = bh & 15;
    const int n0 = ntb * 128;
    const int chunks = (flag[0] != 0) ? ((n0 + 128) / JC) : (MM / JC);

    extern __shared__ __half ovs[];
    uint32_t s0 = (uint32_t)__cvta_generic_to_shared(ovs);

    const int tid = threadIdx.x;
    const int lane = tid & 31, warp = tid >> 5;
    const int g = lane >> 2, t = lane & 3;
    const int wy = warp >> 1;            // n-dir 0..3
    const int wx = warp & 1;             // d-dir 0..1

    const char* Pbytes = (const char*)(g_S + ((size_t)bh * NN + n0) * MM);
    const __half* Vb = g_V16 + (size_t)b * MM * DD + h * HD;

    float acc[2][4][4];
#pragma unroll
    for (int i = 0; i < 2; i++)
#pragma unroll
        for (int j = 0; j < 4; j++)
#pragma unroll
            for (int p = 0; p < 4; p++) acc[i][j][p] = 0.f;

    auto load_chunk = [&](int c, int buf) {
        const int j0 = c * JC;
#pragma unroll
        for (int i = 0; i < 4; i++) {
            int idx = tid + i * 256;            // 0..1023
            int r = idx >> 3, seg = idx & 7;    // row, 16B segment
            const char* psrc = Pbytes + (size_t)r * (MM * 4) + j0 * 2 + seg * 16;
            uint32_t d = (uint32_t)(buf * OV_PS + r * PROW) * 2 + seg * 16;
            cp16(s0 + d, psrc);
        }
#pragma unroll
        for (int i = 0; i < 2; i++) {
            int idx = tid + i * 256;            // 0..511
            int r = idx >> 3, seg = idx & 7;
            size_t voff = (size_t)(j0 + r) * DD + seg * 8;
            uint32_t d = (uint32_t)(buf * OV_VS + r * VROW) * 2 + seg * 16;
            cp16(s0 + OV_OFF_VS * 2 + d, Vb + voff);
        }
    };

    load_chunk(0, 0);
    cp_commit();

    for (int c = 0; c < chunks; c++) {
        const int buf = c & 1;
        if (c + 1 < chunks) {
            load_chunk(c + 1, buf ^ 1);
            cp_commit();
            cp_wait1();
        } else {
            cp_wait0();
        }
        __syncthreads();

        const __half* PP = ovs + buf * OV_PS;
        const __half* VV = ovs + OV_OFF_VS + buf * OV_VS;

#pragma unroll
        for (int ks = 0; ks < 4; ks++) {
            const int jb = ks * 16;
            uint32_t ap[2][4];
#pragma unroll
            for (int mt = 0; mt < 2; mt++) {
                int rr = wy * 32 + mt * 16 + g;
                ap[mt][0] = *(const uint32_t*)&PP[rr * PROW + jb + 2 * t];
                ap[mt][1] = *(const uint32_t*)&PP[(rr + 8) * PROW + jb + 2 * t];
                ap[mt][2] = *(const uint32_t*)&PP[rr * PROW + jb + 8 + 2 * t];
                ap[mt][3] = *(const uint32_t*)&PP[(rr + 8) * PROW + jb + 8 + 2 * t];
            }
#pragma unroll
            for (int nt = 0; nt < 4; nt++) {
                int dd = wx * 32 + nt * 8 + g;
                uint32_t b0 = (uint32_t)*(const unsigned short*)&VV[(jb + 2 * t) * VROW + dd]
                            | ((uint32_t)*(const unsigned short*)&VV[(jb + 2 * t + 1) * VROW + dd] << 16);
                uint32_t b1 = (uint32_t)*(const unsigned short*)&VV[(jb + 8 + 2 * t) * VROW + dd]
                            | ((uint32_t)*(const unsigned short*)&VV[(jb + 9 + 2 * t) * VROW + dd] << 16);
#pragma unroll
                for (int mt = 0; mt < 2; mt++) {
                    float* d = acc[mt][nt];
                    MMA_F16(d, ap[mt][0], ap[mt][1], ap[mt][2], ap[mt][3], b0, b1);
                }
            }
        }
        __syncthreads();
    }

#pragma unroll
    for (int mt = 0; mt < 2; mt++) {
        int r0 = n0 + wy * 32 + mt * 16 + g;
        int r1 = r0 + 8;
#pragma unroll
        for (int nt = 0; nt < 4; nt++) {
            int col = h * HD + wx * 32 + nt * 8 + 2 * t;
            float* d = acc[mt][nt];
            *(float2*)&g_O[((size_t)b * NN + r0) * DD + col] = make_float2(d[0], d[1]);
            *(float2*)&g_O[((size_t)b * NN + r1) * DD + col] = make_float2(d[2], d[3]);
        }
    }
}

// ---------------------------------------------------------------------------
// Launch
// ---------------------------------------------------------------------------
extern "C" void kernel_launch(void* const* d_in, const int* in_sizes, int n_in,
                              void* d_out, int out_size)
{
    const float* query = (const float*)d_in[0];
    const float* key   = (const float*)d_in[1];
    const float* value = (const float*)d_in[2];
    const int*   kpl   = (const int*)d_in[3];
    const int*   flag  = (const int*)d_in[4];
    const float* wq_w  = (const float*)d_in[5];
    const float* wq_b  = (const float*)d_in[6];
    const float* wk_w  = (const float*)d_in[7];
    const float* wk_b  = (const float*)d_in[8];
    const float* wv_w  = (const float*)d_in[9];
    const float* wv_b  = (const float*)d_in[10];
    const float* wo_w  = (const float*)d_in[11];
    const float* wo_b  = (const float*)d_in[12];
    float* out = (float*)d_out;

    static bool attr_done = false;
    if (!attr_done) {
        cudaFuncSetAttribute(qkv_mma,    cudaFuncAttributeMaxDynamicSharedMemorySize, SMEMB);
        cudaFuncSetAttribute(proj_mma,   cudaFuncAttributeMaxDynamicSharedMemorySize, SMEMB);
        cudaFuncSetAttribute(scores_mma, cudaFuncAttributeMaxDynamicSharedMemorySize, SMEMB);
        cudaFuncSetAttribute(attn_ov,    cudaFuncAttributeMaxDynamicSharedMemorySize, OV_SMEMB);
        attr_done = true;
    }

    float *Op;
    cudaGetSymbolAddress((void**)&Op, g_O);

    qkv_mma<<<dim3(32, 24), 256, SMEMB>>>(query, key, value,
                                          wq_w, wk_w, wv_w,
                                          wq_b, wk_b, wv_b, kpl);

    scores_mma<<<dim3(16, 16, 32), 256, SMEMB>>>(flag);

    const long long need = (long long)BB * NN * DD + (long long)BB * NN * MM;
    float* wout = ((long long)out_size >= need) ? (out + (size_t)BB * NN * DD)
                                                : nullptr;
    softmax_wmean<<<BB * NN, 256>>>(flag, wout);

    attn_ov<<<dim3(16, 32), 256, OV_SMEMB>>>(flag);

    proj_mma<<<dim3(32, 8), 256, SMEMB>>>(Op, wo_w, wo_b, out);
}

// round 16
// speedup vs baseline: 1.2732x; 1.0719x over previous
#include <cuda_runtime.h>
#include <cuda_bf16.h>
#include <cuda_fp16.h>
#include <math.h>
#include <stdint.h>

// Problem constants
#define BB 2
#define NN 2048
#define MM 2048
#define DD 1024
#define HH 16
#define HD 64
#define SCALE 0.125f   // 1/sqrt(64)

#define SROW 20        // smem row stride (floats) for 16-wide k tile + pad
#define STAGES 3
#define TILEF (128 * SROW)                 // floats per tile-stage
#define SMEMB (STAGES * 2 * TILEF * 4)     // dynamic smem bytes (61440)

// Scores panel kernel geometry (fp16)
#define SCROW 72                            // smem row stride (halfs) for 64-wide rows
#define SC_QS (128 * SCROW)                 // halfs for Q panel
#define SC_KS (128 * SCROW)                 // halfs per K buffer
#define SC_SMEMB ((SC_QS + 2 * SC_KS) * 2)  // 55296 bytes

// OV kernel geometry (fp16 pipeline, single-V)
#define JC 64                               // j-chunk
#define PROW 72                             // P smem row stride (fp16)
#define VROW 72                             // V smem row stride (fp16)
#define OV_PS (128 * PROW)                  // halfs per P buf
#define OV_VS (64 * VROW)                   // halfs per V buf
#define OV_OFF_VS (2 * OV_PS)
#define OV_SMEMB ((2 * OV_PS + 2 * OV_VS) * 2)   // 55296 bytes

typedef __nv_bfloat16 bf16;
typedef __nv_bfloat162 bf162;

// ---------------------------------------------------------------------------
// Scratch (allocation-free rule: __device__ globals)
// ---------------------------------------------------------------------------
__device__ __half g_Qh[(size_t)BB * NN * DD];         // 8 MB (Q fp16)
__device__ __half g_Kh[(size_t)BB * MM * DD];         // 8 MB (K fp16)
__device__ __half g_V16[(size_t)BB * MM * DD];        // 8 MB (V fp16)
__device__ float  g_O[(size_t)BB * NN * DD];          // 16 MB
// S fp32 (scores); softmax rewrites each row in place: bytes [0,4096) =
// P fp16[2048], rest of the 8KB row unused.
__device__ float g_S[(size_t)BB * HH * NN * MM];      // 512 MB

// ---------------------------------------------------------------------------
// split helpers
// ---------------------------------------------------------------------------
__device__ __forceinline__ void split_bf16x2(float2 v, uint32_t& hi, uint32_t& lo) {
    bf162 h = __float22bfloat162_rn(v);
    float2 hf = __bfloat1622float2(h);
    bf162 l = __float22bfloat162_rn(make_float2(v.x - hf.x, v.y - hf.y));
    hi = *(uint32_t*)&h;
    lo = *(uint32_t*)&l;
}

#define MMA_BF16(d, a0, a1, a2, a3, b0, b1)                                \
    asm volatile("mma.sync.aligned.m16n8k16.row.col.f32.bf16.bf16.f32 "    \
        "{%0,%1,%2,%3}, {%4,%5,%6,%7}, {%8,%9}, {%0,%1,%2,%3};"            \
        : "+f"(d[0]), "+f"(d[1]), "+f"(d[2]), "+f"(d[3])                   \
        : "r"(a0), "r"(a1), "r"(a2), "r"(a3), "r"(b0), "r"(b1))

#define MMA_F16(d, a0, a1, a2, a3, b0, b1)                                 \
    asm volatile("mma.sync.aligned.m16n8k16.row.col.f32.f16.f16.f32 "      \
        "{%0,%1,%2,%3}, {%4,%5,%6,%7}, {%8,%9}, {%0,%1,%2,%3};"            \
        : "+f"(d[0]), "+f"(d[1]), "+f"(d[2]), "+f"(d[3])                   \
        : "r"(a0), "r"(a1), "r"(a2), "r"(a3), "r"(b0), "r"(b1))

__device__ __forceinline__ void cp16(uint32_t dst, const void* src) {
    asm volatile("cp.async.ca.shared.global [%0], [%1], 16;" :: "r"(dst), "l"(src));
}
__device__ __forceinline__ void cp_commit() { asm volatile("cp.async.commit_group;"); }
__device__ __forceinline__ void cp_wait2()  { asm volatile("cp.async.wait_group 2;"); }
__device__ __forceinline__ void cp_wait1()  { asm volatile("cp.async.wait_group 1;"); }
__device__ __forceinline__ void cp_wait0()  { asm volatile("cp.async.wait_group 0;"); }

// Load one 128x16 fp32 tile into one smem stage.
__device__ __forceinline__ void load_tile16(uint32_t s_base, const float* gsrc,
                                            int ld, int k0, int tid) {
    int r0 = tid >> 2, kc0 = (tid & 3) * 4;
    cp16(s_base + (uint32_t)(r0 * SROW + kc0) * 4, gsrc + (size_t)r0 * ld + k0 + kc0);
    int c1 = tid + 256;
    int r1 = c1 >> 2, kc1 = (c1 & 3) * 4;
    cp16(s_base + (uint32_t)(r1 * SROW + kc1) * 4, gsrc + (size_t)r1 * ld + k0 + kc1);
}

// ---------------------------------------------------------------------------
// Shared 3-term bf16 mainloop (3-stage cp.async pipeline) — fp32 inputs.
// Used by qkv and wo projections.
// ---------------------------------------------------------------------------
__device__ __forceinline__ void mma3_mainloop(
    const float* __restrict__ Ab, int lda,
    const float* __restrict__ Bb, int ldb, int ktiles,
    float* sa, float* sb, float (&acc)[4][4][4], int tid)
{
    const int lane = tid & 31;
    const int warp = tid >> 5;
    const int g = lane >> 2, t = lane & 3;
    const int wm0 = (warp >> 2) * 64;
    const int wn0 = (warp & 3) * 32;

    uint32_t sA = (uint32_t)__cvta_generic_to_shared(sa);
    uint32_t sB = (uint32_t)__cvta_generic_to_shared(sb);
    const uint32_t stB = TILEF * 4;

    load_tile16(sA, Ab, lda, 0, tid);
    load_tile16(sB, Bb, ldb, 0, tid);
    cp_commit();
    if (ktiles > 1) {
        load_tile16(sA + stB, Ab, lda, 16, tid);
        load_tile16(sB + stB, Bb, ldb, 16, tid);
    }
    cp_commit();

    for (int c = 0; c < ktiles; c++) {
        const int buf = c % 3;
        if (c + 2 < ktiles) {
            uint32_t off = ((c + 2) % 3) * stB;
            load_tile16(sA + off, Ab, lda, (c + 2) * 16, tid);
            load_tile16(sB + off, Bb, ldb, (c + 2) * 16, tid);
            cp_commit();
            cp_wait2();
        } else if (c + 1 < ktiles) {
            cp_wait1();
        } else {
            cp_wait0();
        }
        __syncthreads();

        const float* A3 = sa + buf * TILEF;
        const float* B3 = sb + buf * TILEF;

        uint32_t ah[4][4], al[4][4];
#pragma unroll
        for (int mt = 0; mt < 4; mt++) {
            int rr = wm0 + mt * 16 + g;
            float2 p00 = *(const float2*)&A3[rr * SROW + 2 * t];
            float2 p10 = *(const float2*)&A3[(rr + 8) * SROW + 2 * t];
            float2 p01 = *(const float2*)&A3[rr * SROW + 8 + 2 * t];
            float2 p11 = *(const float2*)&A3[(rr + 8) * SROW + 8 + 2 * t];
            split_bf16x2(p00, ah[mt][0], al[mt][0]);
            split_bf16x2(p10, ah[mt][1], al[mt][1]);
            split_bf16x2(p01, ah[mt][2], al[mt][2]);
            split_bf16x2(p11, ah[mt][3], al[mt][3]);
        }
#pragma unroll
        for (int nt = 0; nt < 4; nt++) {
            int cc = wn0 + nt * 8 + g;
            float2 q0 = *(const float2*)&B3[cc * SROW + 2 * t];
            float2 q1 = *(const float2*)&B3[cc * SROW + 8 + 2 * t];
            uint32_t bh0, bl0, bh1, bl1;
            split_bf16x2(q0, bh0, bl0);
            split_bf16x2(q1, bh1, bl1);
#pragma unroll
            for (int mt = 0; mt < 4; mt++) {
                float* d = acc[mt][nt];
                MMA_BF16(d, ah[mt][0], ah[mt][1], ah[mt][2], ah[mt][3], bh0, bh1);
                MMA_BF16(d, ah[mt][0], ah[mt][1], ah[mt][2], ah[mt][3], bl0, bl1);
                MMA_BF16(d, al[mt][0], al[mt][1], al[mt][2], al[mt][3], bh0, bh1);
            }
        }
        __syncthreads();
    }
}

// fp32 epilogue: add bias (used by wo projection).
__device__ __forceinline__ void proj_epilogue(
    float (&acc)[4][4][4], const float* __restrict__ bias,
    float* __restrict__ C, int m0, int n0, int tid)
{
    const int lane = tid & 31;
    const int warp = tid >> 5;
    const int g = lane >> 2, t = lane & 3;
    const int wm0 = (warp >> 2) * 64;
    const int wn0 = (warp & 3) * 32;

#pragma unroll
    for (int mt = 0; mt < 4; mt++) {
        int r0 = m0 + wm0 + mt * 16 + g;
        int r1 = r0 + 8;
#pragma unroll
        for (int nt = 0; nt < 4; nt++) {
            int col = n0 + wn0 + nt * 8 + 2 * t;
            float2 bi = *(const float2*)&bias[col];
            float* d = acc[mt][nt];
            *(float2*)&C[(size_t)r0 * DD + col] = make_float2(d[0] + bi.x, d[1] + bi.y);
            *(float2*)&C[(size_t)r1 * DD + col] = make_float2(d[2] + bi.x, d[3] + bi.y);
        }
    }
}

// ---------------------------------------------------------------------------
// Fused Q/K/V projection: grid (32, 24). Segment = blockIdx.y >> 3.
// All three outputs stored as single fp16 (Q/K feed fp16 scores, V feeds OV).
// K rows zeroed per key_padding (exact in fp16).
// ---------------------------------------------------------------------------
__global__ __launch_bounds__(256, 2) void qkv_mma(
    const float* __restrict__ q_in, const float* __restrict__ k_in,
    const float* __restrict__ v_in,
    const float* __restrict__ wq, const float* __restrict__ wk,
    const float* __restrict__ wv,
    const float* __restrict__ bq, const float* __restrict__ bk,
    const float* __restrict__ bv,
    const int* __restrict__ kpl)
{
    extern __shared__ float smem[];
    float* sa = smem;
    float* sb = smem + STAGES * TILEF;

    const int tid = threadIdx.x;
    const int seg = blockIdx.y >> 3;
    const int n0 = (blockIdx.y & 7) * 128;
    const int m0 = blockIdx.x * 128;

    const float* A    = (seg == 0) ? q_in : (seg == 1) ? k_in : v_in;
    const float* W    = (seg == 0) ? wq   : (seg == 1) ? wk   : wv;
    const float* bias = (seg == 0) ? bq   : (seg == 1) ? bk   : bv;
    __half* C = (seg == 0) ? g_Qh : (seg == 1) ? g_Kh : g_V16;
    const int* pad = (seg == 1) ? kpl : nullptr;

    float acc[4][4][4];
#pragma unroll
    for (int i = 0; i < 4; i++)
#pragma unroll
        for (int j = 0; j < 4; j++)
#pragma unroll
            for (int p = 0; p < 4; p++) acc[i][j][p] = 0.f;

    mma3_mainloop(A + (size_t)m0 * DD, DD, W + (size_t)n0 * DD, DD,
                  64, sa, sb, acc, tid);

    const int lane = tid & 31;
    const int warp = tid >> 5;
    const int g = lane >> 2, t = lane & 3;
    const int wm0 = (warp >> 2) * 64;
    const int wn0 = (warp & 3) * 32;
#pragma unroll
    for (int mt = 0; mt < 4; mt++) {
        int r0 = m0 + wm0 + mt * 16 + g;
        int r1 = r0 + 8;
        bool z0 = false, z1 = false;
        if (pad != nullptr) {
            z0 = ((r0 & 2047) >= MM - pad[r0 >> 11]);
            z1 = ((r1 & 2047) >= MM - pad[r1 >> 11]);
        }
#pragma unroll
        for (int nt = 0; nt < 4; nt++) {
            int col = n0 + wn0 + nt * 8 + 2 * t;
            float2 bi = *(const float2*)&bias[col];
            float* d = acc[mt][nt];
            __half2 h0 = z0 ? __half2half2(__float2half(0.f))
                            : __float22half2_rn(make_float2(d[0] + bi.x, d[1] + bi.y));
            __half2 h1 = z1 ? __half2half2(__float2half(0.f))
                            : __float22half2_rn(make_float2(d[2] + bi.x, d[3] + bi.y));
            *(__half2*)&C[(size_t)r0 * DD + col] = h0;
            *(__half2*)&C[(size_t)r1 * DD + col] = h1;
        }
    }
}

// ---------------------------------------------------------------------------
// Output projection: C = A @ W^T + bias (fp32 in/out). Grid (32, 8).
// ---------------------------------------------------------------------------
__global__ __launch_bounds__(256, 2) void proj_mma(
    const float* __restrict__ A, const float* __restrict__ W,
    const float* __restrict__ bias, float* __restrict__ C)
{
    extern __shared__ float smem[];
    float* sa = smem;
    float* sb = smem + STAGES * TILEF;

    const int tid = threadIdx.x;
    const int m0 = blockIdx.x * 128;
    const int n0 = blockIdx.y * 128;

    float acc[4][4][4];
#pragma unroll
    for (int i = 0; i < 4; i++)
#pragma unroll
        for (int j = 0; j < 4; j++)
#pragma unroll
            for (int p = 0; p < 4; p++) acc[i][j][p] = 0.f;

    mma3_mainloop(A + (size_t)m0 * DD, DD, W + (size_t)n0 * DD, DD,
                  64, sa, sb, acc, tid);
    proj_epilogue(acc, bias, C, m0, n0, tid);
}

// ---------------------------------------------------------------------------
// Scores, fp16 panel kernel. Grid (16, 32) = (ntb, bh), heavy-first.
// CTA keeps its Q panel (128 rows x 64, fp16) in smem and streams K tiles
// (double-buffered cp.async) across mt = 0..mtmax-1. Single fp16 MMA term.
// S written fp32 (softmax input unchanged).
// ---------------------------------------------------------------------------
__global__ __launch_bounds__(256, 2) void scores_f16(const int* __restrict__ flag)
{
    const int ntb = gridDim.x - 1 - blockIdx.x;   // heavy first
    const int bh = blockIdx.y;
    const int b = bh >> 4, h = bh & 15;
    const int n0 = ntb * 128;
    const int mtmax = (flag[0] != 0) ? (ntb + 1) : (MM >> 7);

    extern __shared__ __half sc[];
    __half* Qs = sc;                      // [128][SCROW]
    __half* Ks = sc + SC_QS;              // [2][128][SCROW]
    uint32_t sQ = (uint32_t)__cvta_generic_to_shared(Qs);
    uint32_t sK = (uint32_t)__cvta_generic_to_shared(Ks);

    const int tid = threadIdx.x;
    const int lane = tid & 31, warp = tid >> 5;
    const int g = lane >> 2, t = lane & 3;
    const int wm0 = (warp >> 2) * 64;     // query-row dir
    const int wn0 = (warp & 3) * 32;      // key-col dir

    const __half* Qb = g_Qh + (size_t)b * NN * DD + (size_t)n0 * DD + h * HD;
    const __half* Kb = g_Kh + (size_t)b * MM * DD + h * HD;
    float* Sbase = g_S + (size_t)bh * NN * MM;

    // loaders: 128 rows x 128B = 1024 cp16 -> 4 per thread
    auto load_panel = [&](uint32_t sdst, const __half* gsrc) {
#pragma unroll
        for (int i = 0; i < 4; i++) {
            int idx = tid + i * 256;
            int r = idx >> 3, seg = idx & 7;
            cp16(sdst + (uint32_t)(r * SCROW * 2 + seg * 16),
                 gsrc + (size_t)r * DD + seg * 8);
        }
    };

    load_panel(sQ, Qb);
    cp_commit();
    load_panel(sK, Kb);                   // K tile 0
    cp_commit();

    for (int mt = 0; mt < mtmax; mt++) {
        const int buf = mt & 1;
        if (mt + 1 < mtmax) {
            load_panel(sK + (buf ^ 1) * SC_KS * 2,
                       Kb + (size_t)(mt + 1) * 128 * DD);
            cp_commit();
            cp_wait1();
        } else {
            cp_wait0();
        }
        __syncthreads();

        const __half* Kt = Ks + buf * SC_KS;

        float acc[4][4][4];
#pragma unroll
        for (int i = 0; i < 4; i++)
#pragma unroll
            for (int j = 0; j < 4; j++)
#pragma unroll
                for (int p = 0; p < 4; p++) acc[i][j][p] = 0.f;

#pragma unroll
        for (int ks = 0; ks < 4; ks++) {
            const int jb = ks * 16;
            uint32_t aq[4][4];
#pragma unroll
            for (int mi = 0; mi < 4; mi++) {
                int rr = wm0 + mi * 16 + g;
                aq[mi][0] = *(const uint32_t*)&Qs[rr * SCROW + jb + 2 * t];
                aq[mi][1] = *(const uint32_t*)&Qs[(rr + 8) * SCROW + jb + 2 * t];
                aq[mi][2] = *(const uint32_t*)&Qs[rr * SCROW + jb + 8 + 2 * t];
                aq[mi][3] = *(const uint32_t*)&Qs[(rr + 8) * SCROW + jb + 8 + 2 * t];
            }
#pragma unroll
            for (int nt = 0; nt < 4; nt++) {
                int cc = wn0 + nt * 8 + g;
                uint32_t b0 = *(const uint32_t*)&Kt[cc * SCROW + jb + 2 * t];
                uint32_t b1 = *(const uint32_t*)&Kt[cc * SCROW + jb + 8 + 2 * t];
#pragma unroll
                for (int mi = 0; mi < 4; mi++) {
                    float* d = acc[mi][nt];
                    MMA_F16(d, aq[mi][0], aq[mi][1], aq[mi][2], aq[mi][3], b0, b1);
                }
            }
        }
        __syncthreads();

        const int m0 = mt * 128;
#pragma unroll
        for (int qt = 0; qt < 4; qt++) {
            int r0 = n0 + wm0 + qt * 16 + g;
            int r1 = r0 + 8;
#pragma unroll
            for (int kt = 0; kt < 4; kt++) {
                int col = m0 + wn0 + kt * 8 + 2 * t;
                float* d = acc[qt][kt];
                *(float2*)&Sbase[(size_t)r0 * MM + col] =
                    make_float2(d[0] * SCALE, d[1] * SCALE);
                *(float2*)&Sbase[(size_t)r1 * MM + col] =
                    make_float2(d[2] * SCALE, d[3] * SCALE);
            }
        }
    }
}

// ---------------------------------------------------------------------------
// Fused softmax + head-mean, heavy rows first. Rewrites each P row IN PLACE
// as fp16[2048] in the row's first 4KB; zero-padded to 128-boundary.
// wmean accumulated in fp32 BEFORE the fp16 conversion (exact).
// ---------------------------------------------------------------------------
__global__ __launch_bounds__(256) void softmax_wmean(const int* __restrict__ flag,
                                                     float* __restrict__ wout)
{
    const int blk = blockIdx.x;
    const int b = blk >> 11;
    const int n = NN - 1 - (blk & (NN - 1));
    const int causal = (flag[0] != 0);
    const int len    = causal ? (n + 1) : MM;
    const int lenpad = causal ? min((((n >> 7) + 1) << 7), MM) : MM;
    const int tid = threadIdx.x;
    const float NEGINF = __int_as_float(0xff800000);

    __shared__ float red[8];
    float2 wacc[4];
#pragma unroll
    for (int k = 0; k < 4; k++) wacc[k] = make_float2(0.f, 0.f);

    for (int h = 0; h < HH; h++) {
        float* row = g_S + (((size_t)(b * HH + h) * NN) + n) * MM;

        float2 v2[4];
        float mx = NEGINF;
#pragma unroll
        for (int k = 0; k < 4; k++) {
            int j2 = tid * 2 + k * 512;
            float2 s = *(const float2*)&row[j2];
            s.x = (j2     < len) ? s.x : NEGINF;
            s.y = (j2 + 1 < len) ? s.y : NEGINF;
            v2[k] = s;
            mx = fmaxf(mx, fmaxf(s.x, s.y));
        }
#pragma unroll
        for (int o = 16; o > 0; o >>= 1)
            mx = fmaxf(mx, __shfl_xor_sync(0xffffffffu, mx, o));
        if ((tid & 31) == 0) red[tid >> 5] = mx;
        __syncthreads();
        float bm = red[0];
#pragma unroll
        for (int w = 1; w < 8; w++) bm = fmaxf(bm, red[w]);
        __syncthreads();

        float sum = 0.f;
#pragma unroll
        for (int k = 0; k < 4; k++) {
            v2[k].x = expf(v2[k].x - bm);
            v2[k].y = expf(v2[k].y - bm);
            sum += v2[k].x + v2[k].y;
        }
#pragma unroll
        for (int o = 16; o > 0; o >>= 1)
            sum += __shfl_xor_sync(0xffffffffu, sum, o);
        if ((tid & 31) == 0) red[tid >> 5] = sum;
        __syncthreads();
        float tot = red[0];
#pragma unroll
        for (int w = 1; w < 8; w++) tot += red[w];
        __syncthreads();
        float inv = 1.0f / tot;

        uint32_t* rowW = (uint32_t*)row;
#pragma unroll
        for (int k = 0; k < 4; k++) {
            int j2 = tid * 2 + k * 512;
            float2 p = make_float2(v2[k].x * inv, v2[k].y * inv);
            wacc[k].x += p.x;
            wacc[k].y += p.y;
            if (j2 < lenpad) {
                __half2 ph = __float22half2_rn(p);
                rowW[j2 >> 1] = *(uint32_t*)&ph;
            }
        }
    }

    if (wout != nullptr) {
        float* orow = wout + ((size_t)b * NN + n) * MM;
#pragma unroll
        for (int k = 0; k < 4; k++) {
            int j2 = tid * 2 + k * 512;
            *(float2*)&orow[j2] = make_float2(wacc[k].x * (1.0f / HH),
                                              wacc[k].y * (1.0f / HH));
        }
    }
}

// ---------------------------------------------------------------------------
// OV on tensor cores: P fp16 x V fp16, single MMA term.
// j-chunk 64, double-buffered, heavy blocks first, 3 CTAs/SM.
// ---------------------------------------------------------------------------
__global__ __launch_bounds__(256, 3) void attn_ov(const int* __restrict__ flag)
{
    const int ntb = gridDim.x - 1 - blockIdx.x;   // heavy first
    const int bh = blockIdx.y;
    const int b = bh >> 4, h = bh & 15;
    const int n0 = ntb * 128;
    const int chunks = (flag[0] != 0) ? ((n0 + 128) / JC) : (MM / JC);

    extern __shared__ __half ovs[];
    uint32_t s0 = (uint32_t)__cvta_generic_to_shared(ovs);

    const int tid = threadIdx.x;
    const int lane = tid & 31, warp = tid >> 5;
    const int g = lane >> 2, t = lane & 3;
    const int wy = warp >> 1;            // n-dir 0..3
    const int wx = warp & 1;             // d-dir 0..1

    const char* Pbytes = (const char*)(g_S + ((size_t)bh * NN + n0) * MM);
    const __half* Vb = g_V16 + (size_t)b * MM * DD + h * HD;

    float acc[2][4][4];
#pragma unroll
    for (int i = 0; i < 2; i++)
#pragma unroll
        for (int j = 0; j < 4; j++)
#pragma unroll
            for (int p = 0; p < 4; p++) acc[i][j][p] = 0.f;

    auto load_chunk = [&](int c, int buf) {
        const int j0 = c * JC;
#pragma unroll
        for (int i = 0; i < 4; i++) {
            int idx = tid + i * 256;            // 0..1023
            int r = idx >> 3, seg = idx & 7;    // row, 16B segment
            const char* psrc = Pbytes + (size_t)r * (MM * 4) + j0 * 2 + seg * 16;
            uint32_t d = (uint32_t)(buf * OV_PS + r * PROW) * 2 + seg * 16;
            cp16(s0 + d, psrc);
        }
#pragma unroll
        for (int i = 0; i < 2; i++) {
            int idx = tid + i * 256;            // 0..511
            int r = idx >> 3, seg = idx & 7;
            size_t voff = (size_t)(j0 + r) * DD + seg * 8;
            uint32_t d = (uint32_t)(buf * OV_VS + r * VROW) * 2 + seg * 16;
            cp16(s0 + OV_OFF_VS * 2 + d, Vb + voff);
        }
    };

    load_chunk(0, 0);
    cp_commit();

    for (int c = 0; c < chunks; c++) {
        const int buf = c & 1;
        if (c + 1 < chunks) {
            load_chunk(c + 1, buf ^ 1);
            cp_commit();
            cp_wait1();
        } else {
            cp_wait0();
        }
        __syncthreads();

        const __half* PP = ovs + buf * OV_PS;
        const __half* VV = ovs + OV_OFF_VS + buf * OV_VS;

#pragma unroll
        for (int ks = 0; ks < 4; ks++) {
            const int jb = ks * 16;
            uint32_t ap[2][4];
#pragma unroll
            for (int mt = 0; mt < 2; mt++) {
                int rr = wy * 32 + mt * 16 + g;
                ap[mt][0] = *(const uint32_t*)&PP[rr * PROW + jb + 2 * t];
                ap[mt][1] = *(const uint32_t*)&PP[(rr + 8) * PROW + jb + 2 * t];
                ap[mt][2] = *(const uint32_t*)&PP[rr * PROW + jb + 8 + 2 * t];
                ap[mt][3] = *(const uint32_t*)&PP[(rr + 8) * PROW + jb + 8 + 2 * t];
            }
#pragma unroll
            for (int nt = 0; nt < 4; nt++) {
                int dd = wx * 32 + nt * 8 + g;
                uint32_t b0 = (uint32_t)*(const unsigned short*)&VV[(jb + 2 * t) * VROW + dd]
                            | ((uint32_t)*(const unsigned short*)&VV[(jb + 2 * t + 1) * VROW + dd] << 16);
                uint32_t b1 = (uint32_t)*(const unsigned short*)&VV[(jb + 8 + 2 * t) * VROW + dd]
                            | ((uint32_t)*(const unsigned short*)&VV[(jb + 9 + 2 * t) * VROW + dd] << 16);
#pragma unroll
                for (int mt = 0; mt < 2; mt++) {
                    float* d = acc[mt][nt];
                    MMA_F16(d, ap[mt][0], ap[mt][1], ap[mt][2], ap[mt][3], b0, b1);
                }
            }
        }
        __syncthreads();
    }

#pragma unroll
    for (int mt = 0; mt < 2; mt++) {
        int r0 = n0 + wy * 32 + mt * 16 + g;
        int r1 = r0 + 8;
#pragma unroll
        for (int nt = 0; nt < 4; nt++) {
            int col = h * HD + wx * 32 + nt * 8 + 2 * t;
            float* d = acc[mt][nt];
            *(float2*)&g_O[((size_t)b * NN + r0) * DD + col] = make_float2(d[0], d[1]);
            *(float2*)&g_O[((size_t)b * NN + r1) * DD + col] = make_float2(d[2], d[3]);
        }
    }
}

// ---------------------------------------------------------------------------
// Launch
// ---------------------------------------------------------------------------
extern "C" void kernel_launch(void* const* d_in, const int* in_sizes, int n_in,
                              void* d_out, int out_size)
{
    const float* query = (const float*)d_in[0];
    const float* key   = (const float*)d_in[1];
    const float* value = (const float*)d_in[2];
    const int*   kpl   = (const int*)d_in[3];
    const int*   flag  = (const int*)d_in[4];
    const float* wq_w  = (const float*)d_in[5];
    const float* wq_b  = (const float*)d_in[6];
    const float* wk_w  = (const float*)d_in[7];
    const float* wk_b  = (const float*)d_in[8];
    const float* wv_w  = (const float*)d_in[9];
    const float* wv_b  = (const float*)d_in[10];
    const float* wo_w  = (const float*)d_in[11];
    const float* wo_b  = (const float*)d_in[12];
    float* out = (float*)d_out;

    static bool attr_done = false;
    if (!attr_done) {
        cudaFuncSetAttribute(qkv_mma,    cudaFuncAttributeMaxDynamicSharedMemorySize, SMEMB);
        cudaFuncSetAttribute(proj_mma,   cudaFuncAttributeMaxDynamicSharedMemorySize, SMEMB);
        cudaFuncSetAttribute(scores_f16, cudaFuncAttributeMaxDynamicSharedMemorySize, SC_SMEMB);
        cudaFuncSetAttribute(attn_ov,    cudaFuncAttributeMaxDynamicSharedMemorySize, OV_SMEMB);
        attr_done = true;
    }

    float *Op;
    cudaGetSymbolAddress((void**)&Op, g_O);

    qkv_mma<<<dim3(32, 24), 256, SMEMB>>>(query, key, value,
                                          wq_w, wk_w, wv_w,
                                          wq_b, wk_b, wv_b, kpl);

    scores_f16<<<dim3(16, 32), 256, SC_SMEMB>>>(flag);

    const long long need = (long long)BB * NN * DD + (long long)BB * NN * MM;
    float* wout = ((long long)out_size >= need) ? (out + (size_t)BB * NN * DD)
                                                : nullptr;
    softmax_wmean<<<BB * NN, 256>>>(flag, wout);

    attn_ov<<<dim3(16, 32), 256, OV_SMEMB>>>(flag);

    proj_mma<<<dim3(32, 8), 256, SMEMB>>>(Op, wo_w, wo_b, out);
}

// round 17
// speedup vs baseline: 1.4373x; 1.1288x over previous
#include <cuda_runtime.h>
#include <cuda_bf16.h>
#include <cuda_fp16.h>
#include <math.h>
#include <stdint.h>

// Problem constants
#define BB 2
#define NN 2048
#define MM 2048
#define DD 1024
#define HH 16
#define HD 64
#define SCALE 0.125f   // 1/sqrt(64)

#define SROW 20        // smem row stride (floats) for 16-wide k tile + pad
#define STAGES 3
#define TILEF (128 * SROW)                 // floats per tile-stage
#define SMEMB (STAGES * 2 * TILEF * 4)     // dynamic smem bytes (61440)

// Scores panel kernel geometry (fp16)
#define SCROW 72
#define SC_QS (128 * SCROW)
#define SC_KS (128 * SCROW)
#define SC_SMEMB ((SC_QS + 2 * SC_KS) * 2)  // 55296 bytes

// OV kernel geometry (fp16 pipeline, single-V)
#define JC 64
#define PROW 72
#define VROW 72
#define OV_PS (128 * PROW)
#define OV_VS (64 * VROW)
#define OV_OFF_VS (2 * OV_PS)
#define OV_SMEMB ((2 * OV_PS + 2 * OV_VS) * 2)   // 55296 bytes

typedef __nv_bfloat16 bf16;

// ---------------------------------------------------------------------------
// Scratch (allocation-free rule: __device__ globals)
// ---------------------------------------------------------------------------
__device__ __half g_Qh[(size_t)BB * NN * DD];         // 8 MB
__device__ __half g_Kh[(size_t)BB * MM * DD];         // 8 MB
__device__ __half g_V16[(size_t)BB * MM * DD];        // 8 MB
__device__ float  g_O[(size_t)BB * NN * DD];          // 16 MB
// S fp16 [bh][n][m] (scores); softmax rewrites rows in place as P fp16.
__device__ __half g_S16[(size_t)BB * HH * NN * MM];   // 256 MB

// ---------------------------------------------------------------------------
// helpers
// ---------------------------------------------------------------------------
__device__ __forceinline__ void split_h2u(float2 v, uint32_t& hi, uint32_t& lo) {
    __half2 h = __float22half2_rn(v);
    float2 hf = __half22float2(h);
    __half2 l = __float22half2_rn(make_float2(v.x - hf.x, v.y - hf.y));
    hi = *(uint32_t*)&h;
    lo = *(uint32_t*)&l;
}
__device__ __forceinline__ uint32_t pack_h2(float2 v) {
    __half2 h = __float22half2_rn(v);
    return *(uint32_t*)&h;
}

#define MMA_F16(d, a0, a1, a2, a3, b0, b1)                                 \
    asm volatile("mma.sync.aligned.m16n8k16.row.col.f32.f16.f16.f32 "      \
        "{%0,%1,%2,%3}, {%4,%5,%6,%7}, {%8,%9}, {%0,%1,%2,%3};"            \
        : "+f"(d[0]), "+f"(d[1]), "+f"(d[2]), "+f"(d[3])                   \
        : "r"(a0), "r"(a1), "r"(a2), "r"(a3), "r"(b0), "r"(b1))

__device__ __forceinline__ void cp16(uint32_t dst, const void* src) {
    asm volatile("cp.async.ca.shared.global [%0], [%1], 16;" :: "r"(dst), "l"(src));
}
__device__ __forceinline__ void cp_commit() { asm volatile("cp.async.commit_group;"); }
__device__ __forceinline__ void cp_wait2()  { asm volatile("cp.async.wait_group 2;"); }
__device__ __forceinline__ void cp_wait1()  { asm volatile("cp.async.wait_group 1;"); }
__device__ __forceinline__ void cp_wait0()  { asm volatile("cp.async.wait_group 0;"); }

// Load one 128x16 fp32 tile into one smem stage.
__device__ __forceinline__ void load_tile16(uint32_t s_base, const float* gsrc,
                                            int ld, int k0, int tid) {
    int r0 = tid >> 2, kc0 = (tid & 3) * 4;
    cp16(s_base + (uint32_t)(r0 * SROW + kc0) * 4, gsrc + (size_t)r0 * ld + k0 + kc0);
    int c1 = tid + 256;
    int r1 = c1 >> 2, kc1 = (c1 & 3) * 4;
    cp16(s_base + (uint32_t)(r1 * SROW + kc1) * 4, gsrc + (size_t)r1 * ld + k0 + kc1);
}

// ---------------------------------------------------------------------------
// 2-term fp16 mainloop (3-stage cp.async pipeline), fp32 inputs.
// a = ah + al (fp16 pair); b ~ bh (single fp16).
// acc[mt][nt][4] += ah*bh + al*bh  ~= Ablk(128xK) * Bblk(128xK)^T
// ---------------------------------------------------------------------------
__device__ __forceinline__ void mma2_mainloop(
    const float* __restrict__ Ab, int lda,
    const float* __restrict__ Bb, int ldb, int ktiles,
    float* sa, float* sb, float (&acc)[4][4][4], int tid)
{
    const int lane = tid & 31;
    const int warp = tid >> 5;
    const int g = lane >> 2, t = lane & 3;
    const int wm0 = (warp >> 2) * 64;
    const int wn0 = (warp & 3) * 32;

    uint32_t sA = (uint32_t)__cvta_generic_to_shared(sa);
    uint32_t sB = (uint32_t)__cvta_generic_to_shared(sb);
    const uint32_t stB = TILEF * 4;

    load_tile16(sA, Ab, lda, 0, tid);
    load_tile16(sB, Bb, ldb, 0, tid);
    cp_commit();
    if (ktiles > 1) {
        load_tile16(sA + stB, Ab, lda, 16, tid);
        load_tile16(sB + stB, Bb, ldb, 16, tid);
    }
    cp_commit();

    for (int c = 0; c < ktiles; c++) {
        const int buf = c % 3;
        if (c + 2 < ktiles) {
            uint32_t off = ((c + 2) % 3) * stB;
            load_tile16(sA + off, Ab, lda, (c + 2) * 16, tid);
            load_tile16(sB + off, Bb, ldb, (c + 2) * 16, tid);
            cp_commit();
            cp_wait2();
        } else if (c + 1 < ktiles) {
            cp_wait1();
        } else {
            cp_wait0();
        }
        __syncthreads();

        const float* A3 = sa + buf * TILEF;
        const float* B3 = sb + buf * TILEF;

        uint32_t ah[4][4], al[4][4];
#pragma unroll
        for (int mt = 0; mt < 4; mt++) {
            int rr = wm0 + mt * 16 + g;
            split_h2u(*(const float2*)&A3[rr * SROW + 2 * t],        ah[mt][0], al[mt][0]);
            split_h2u(*(const float2*)&A3[(rr + 8) * SROW + 2 * t],  ah[mt][1], al[mt][1]);
            split_h2u(*(const float2*)&A3[rr * SROW + 8 + 2 * t],    ah[mt][2], al[mt][2]);
            split_h2u(*(const float2*)&A3[(rr + 8) * SROW + 8 + 2 * t], ah[mt][3], al[mt][3]);
        }
#pragma unroll
        for (int nt = 0; nt < 4; nt++) {
            int cc = wn0 + nt * 8 + g;
            uint32_t b0 = pack_h2(*(const float2*)&B3[cc * SROW + 2 * t]);
            uint32_t b1 = pack_h2(*(const float2*)&B3[cc * SROW + 8 + 2 * t]);
#pragma unroll
            for (int mt = 0; mt < 4; mt++) {
                float* d = acc[mt][nt];
                MMA_F16(d, ah[mt][0], ah[mt][1], ah[mt][2], ah[mt][3], b0, b1);
                MMA_F16(d, al[mt][0], al[mt][1], al[mt][2], al[mt][3], b0, b1);
            }
        }
        __syncthreads();
    }
}

// fp32 epilogue: add bias (wo projection).
__device__ __forceinline__ void proj_epilogue(
    float (&acc)[4][4][4], const float* __restrict__ bias,
    float* __restrict__ C, int m0, int n0, int tid)
{
    const int lane = tid & 31;
    const int warp = tid >> 5;
    const int g = lane >> 2, t = lane & 3;
    const int wm0 = (warp >> 2) * 64;
    const int wn0 = (warp & 3) * 32;

#pragma unroll
    for (int mt = 0; mt < 4; mt++) {
        int r0 = m0 + wm0 + mt * 16 + g;
        int r1 = r0 + 8;
#pragma unroll
        for (int nt = 0; nt < 4; nt++) {
            int col = n0 + wn0 + nt * 8 + 2 * t;
            float2 bi = *(const float2*)&bias[col];
            float* d = acc[mt][nt];
            *(float2*)&C[(size_t)r0 * DD + col] = make_float2(d[0] + bi.x, d[1] + bi.y);
            *(float2*)&C[(size_t)r1 * DD + col] = make_float2(d[2] + bi.x, d[3] + bi.y);
        }
    }
}

// ---------------------------------------------------------------------------
// Fused Q/K/V projection: grid (32, 24). Segment = blockIdx.y >> 3.
// Outputs stored as single fp16; K rows zeroed per key_padding.
// ---------------------------------------------------------------------------
__global__ __launch_bounds__(256, 2) void qkv_mma(
    const float* __restrict__ q_in, const float* __restrict__ k_in,
    const float* __restrict__ v_in,
    const float* __restrict__ wq, const float* __restrict__ wk,
    const float* __restrict__ wv,
    const float* __restrict__ bq, const float* __restrict__ bk,
    const float* __restrict__ bv,
    const int* __restrict__ kpl)
{
    extern __shared__ float smem[];
    float* sa = smem;
    float* sb = smem + STAGES * TILEF;

    const int tid = threadIdx.x;
    const int seg = blockIdx.y >> 3;
    const int n0 = (blockIdx.y & 7) * 128;
    const int m0 = blockIdx.x * 128;

    const float* A    = (seg == 0) ? q_in : (seg == 1) ? k_in : v_in;
    const float* W    = (seg == 0) ? wq   : (seg == 1) ? wk   : wv;
    const float* bias = (seg == 0) ? bq   : (seg == 1) ? bk   : bv;
    __half* C = (seg == 0) ? g_Qh : (seg == 1) ? g_Kh : g_V16;
    const int* pad = (seg == 1) ? kpl : nullptr;

    float acc[4][4][4];
#pragma unroll
    for (int i = 0; i < 4; i++)
#pragma unroll
        for (int j = 0; j < 4; j++)
#pragma unroll
            for (int p = 0; p < 4; p++) acc[i][j][p] = 0.f;

    mma2_mainloop(A + (size_t)m0 * DD, DD, W + (size_t)n0 * DD, DD,
                  64, sa, sb, acc, tid);

    const int lane = tid & 31;
    const int warp = tid >> 5;
    const int g = lane >> 2, t = lane & 3;
    const int wm0 = (warp >> 2) * 64;
    const int wn0 = (warp & 3) * 32;
#pragma unroll
    for (int mt = 0; mt < 4; mt++) {
        int r0 = m0 + wm0 + mt * 16 + g;
        int r1 = r0 + 8;
        bool z0 = false, z1 = false;
        if (pad != nullptr) {
            z0 = ((r0 & 2047) >= MM - pad[r0 >> 11]);
            z1 = ((r1 & 2047) >= MM - pad[r1 >> 11]);
        }
#pragma unroll
        for (int nt = 0; nt < 4; nt++) {
            int col = n0 + wn0 + nt * 8 + 2 * t;
            float2 bi = *(const float2*)&bias[col];
            float* d = acc[mt][nt];
            __half2 h0 = z0 ? __half2half2(__float2half(0.f))
                            : __float22half2_rn(make_float2(d[0] + bi.x, d[1] + bi.y));
            __half2 h1 = z1 ? __half2half2(__float2half(0.f))
                            : __float22half2_rn(make_float2(d[2] + bi.x, d[3] + bi.y));
            *(__half2*)&C[(size_t)r0 * DD + col] = h0;
            *(__half2*)&C[(size_t)r1 * DD + col] = h1;
        }
    }
}

// ---------------------------------------------------------------------------
// Output projection: C = A @ W^T + bias (fp32 in/out). Grid (32, 8).
// ---------------------------------------------------------------------------
__global__ __launch_bounds__(256, 2) void proj_mma(
    const float* __restrict__ A, const float* __restrict__ W,
    const float* __restrict__ bias, float* __restrict__ C)
{
    extern __shared__ float smem[];
    float* sa = smem;
    float* sb = smem + STAGES * TILEF;

    const int tid = threadIdx.x;
    const int m0 = blockIdx.x * 128;
    const int n0 = blockIdx.y * 128;

    float acc[4][4][4];
#pragma unroll
    for (int i = 0; i < 4; i++)
#pragma unroll
        for (int j = 0; j < 4; j++)
#pragma unroll
            for (int p = 0; p < 4; p++) acc[i][j][p] = 0.f;

    mma2_mainloop(A + (size_t)m0 * DD, DD, W + (size_t)n0 * DD, DD,
                  64, sa, sb, acc, tid);
    proj_epilogue(acc, bias, C, m0, n0, tid);
}

// ---------------------------------------------------------------------------
// Scores, fp16 panel kernel. Grid (16, 32) = (ntb, bh), heavy-first.
// Q panel resident; K tiles streamed double-buffered. S written fp16.
// ---------------------------------------------------------------------------
__global__ __launch_bounds__(256, 2) void scores_f16(const int* __restrict__ flag)
{
    const int ntb = gridDim.x - 1 - blockIdx.x;   // heavy first
    const int bh = blockIdx.y;
    const int b = bh >> 4, h = bh & 15;
    const int n0 = ntb * 128;
    const int mtmax = (flag[0] != 0) ? (ntb + 1) : (MM >> 7);

    extern __shared__ __half sc[];
    __half* Qs = sc;                      // [128][SCROW]
    __half* Ks = sc + SC_QS;              // [2][128][SCROW]
    uint32_t sQ = (uint32_t)__cvta_generic_to_shared(Qs);
    uint32_t sK = (uint32_t)__cvta_generic_to_shared(Ks);

    const int tid = threadIdx.x;
    const int lane = tid & 31, warp = tid >> 5;
    const int g = lane >> 2, t = lane & 3;
    const int wm0 = (warp >> 2) * 64;
    const int wn0 = (warp & 3) * 32;

    const __half* Qb = g_Qh + (size_t)b * NN * DD + (size_t)n0 * DD + h * HD;
    const __half* Kb = g_Kh + (size_t)b * MM * DD + h * HD;
    __half* Sbase = g_S16 + (size_t)bh * NN * MM;

    auto load_panel = [&](uint32_t sdst, const __half* gsrc) {
#pragma unroll
        for (int i = 0; i < 4; i++) {
            int idx = tid + i * 256;
            int r = idx >> 3, seg = idx & 7;
            cp16(sdst + (uint32_t)(r * SCROW * 2 + seg * 16),
                 gsrc + (size_t)r * DD + seg * 8);
        }
    };

    load_panel(sQ, Qb);
    cp_commit();
    load_panel(sK, Kb);
    cp_commit();

    for (int mt = 0; mt < mtmax; mt++) {
        const int buf = mt & 1;
        if (mt + 1 < mtmax) {
            load_panel(sK + (buf ^ 1) * SC_KS * 2,
                       Kb + (size_t)(mt + 1) * 128 * DD);
            cp_commit();
            cp_wait1();
        } else {
            cp_wait0();
        }
        __syncthreads();

        const __half* Kt = Ks + buf * SC_KS;

        float acc[4][4][4];
#pragma unroll
        for (int i = 0; i < 4; i++)
#pragma unroll
            for (int j = 0; j < 4; j++)
#pragma unroll
                for (int p = 0; p < 4; p++) acc[i][j][p] = 0.f;

#pragma unroll
        for (int ks = 0; ks < 4; ks++) {
            const int jb = ks * 16;
            uint32_t aq[4][4];
#pragma unroll
            for (int mi = 0; mi < 4; mi++) {
                int rr = wm0 + mi * 16 + g;
                aq[mi][0] = *(const uint32_t*)&Qs[rr * SCROW + jb + 2 * t];
                aq[mi][1] = *(const uint32_t*)&Qs[(rr + 8) * SCROW + jb + 2 * t];
                aq[mi][2] = *(const uint32_t*)&Qs[rr * SCROW + jb + 8 + 2 * t];
                aq[mi][3] = *(const uint32_t*)&Qs[(rr + 8) * SCROW + jb + 8 + 2 * t];
            }
#pragma unroll
            for (int nt = 0; nt < 4; nt++) {
                int cc = wn0 + nt * 8 + g;
                uint32_t b0 = *(const uint32_t*)&Kt[cc * SCROW + jb + 2 * t];
                uint32_t b1 = *(const uint32_t*)&Kt[cc * SCROW + jb + 8 + 2 * t];
#pragma unroll
                for (int mi = 0; mi < 4; mi++) {
                    float* d = acc[mi][nt];
                    MMA_F16(d, aq[mi][0], aq[mi][1], aq[mi][2], aq[mi][3], b0, b1);
                }
            }
        }
        __syncthreads();

        const int m0 = mt * 128;
#pragma unroll
        for (int qt = 0; qt < 4; qt++) {
            int r0 = n0 + wm0 + qt * 16 + g;
            int r1 = r0 + 8;
#pragma unroll
            for (int kt = 0; kt < 4; kt++) {
                int col = m0 + wn0 + kt * 8 + 2 * t;
                float* d = acc[qt][kt];
                *(__half2*)&Sbase[(size_t)r0 * MM + col] =
                    __float22half2_rn(make_float2(d[0] * SCALE, d[1] * SCALE));
                *(__half2*)&Sbase[(size_t)r1 * MM + col] =
                    __float22half2_rn(make_float2(d[2] * SCALE, d[3] * SCALE));
            }
        }
    }
}

// ---------------------------------------------------------------------------
// Fused softmax + head-mean, heavy rows first. Reads fp16 S rows, rewrites
// each row IN PLACE as fp16 P (zero-padded to 128-boundary). wmean in fp32.
// ---------------------------------------------------------------------------
__global__ __launch_bounds__(256) void softmax_wmean(const int* __restrict__ flag,
                                                     float* __restrict__ wout)
{
    const int blk = blockIdx.x;
    const int b = blk >> 11;
    const int n = NN - 1 - (blk & (NN - 1));
    const int causal = (flag[0] != 0);
    const int len    = causal ? (n + 1) : MM;
    const int lenpad = causal ? min((((n >> 7) + 1) << 7), MM) : MM;
    const int tid = threadIdx.x;
    const float NEGINF = __int_as_float(0xff800000);

    __shared__ float red[8];
    float2 wacc[4];
#pragma unroll
    for (int k = 0; k < 4; k++) wacc[k] = make_float2(0.f, 0.f);

    for (int h = 0; h < HH; h++) {
        __half* row = g_S16 + (((size_t)(b * HH + h) * NN) + n) * MM;

        float2 v2[4];
        float mx = NEGINF;
#pragma unroll
        for (int k = 0; k < 4; k++) {
            int j2 = tid * 2 + k * 512;
            float2 s = __half22float2(*(const __half2*)&row[j2]);
            s.x = (j2     < len) ? s.x : NEGINF;
            s.y = (j2 + 1 < len) ? s.y : NEGINF;
            v2[k] = s;
            mx = fmaxf(mx, fmaxf(s.x, s.y));
        }
#pragma unroll
        for (int o = 16; o > 0; o >>= 1)
            mx = fmaxf(mx, __shfl_xor_sync(0xffffffffu, mx, o));
        if ((tid & 31) == 0) red[tid >> 5] = mx;
        __syncthreads();
        float bm = red[0];
#pragma unroll
        for (int w = 1; w < 8; w++) bm = fmaxf(bm, red[w]);
        __syncthreads();

        float sum = 0.f;
#pragma unroll
        for (int k = 0; k < 4; k++) {
            v2[k].x = expf(v2[k].x - bm);
            v2[k].y = expf(v2[k].y - bm);
            sum += v2[k].x + v2[k].y;
        }
#pragma unroll
        for (int o = 16; o > 0; o >>= 1)
            sum += __shfl_xor_sync(0xffffffffu, sum, o);
        if ((tid & 31) == 0) red[tid >> 5] = sum;
        __syncthreads();
        float tot = red[0];
#pragma unroll
        for (int w = 1; w < 8; w++) tot += red[w];
        __syncthreads();
        float inv = 1.0f / tot;

        uint32_t* rowW = (uint32_t*)row;
#pragma unroll
        for (int k = 0; k < 4; k++) {
            int j2 = tid * 2 + k * 512;
            float2 p = make_float2(v2[k].x * inv, v2[k].y * inv);
            wacc[k].x += p.x;
            wacc[k].y += p.y;
            if (j2 < lenpad) {
                __half2 ph = __float22half2_rn(p);
                rowW[j2 >> 1] = *(uint32_t*)&ph;
            }
        }
    }

    if (wout != nullptr) {
        float* orow = wout + ((size_t)b * NN + n) * MM;
#pragma unroll
        for (int k = 0; k < 4; k++) {
            int j2 = tid * 2 + k * 512;
            *(float2*)&orow[j2] = make_float2(wacc[k].x * (1.0f / HH),
                                              wacc[k].y * (1.0f / HH));
        }
    }
}

// ---------------------------------------------------------------------------
// OV on tensor cores: P fp16 x V fp16, single MMA term.
// j-chunk 64, double-buffered, heavy blocks first, 3 CTAs/SM.
// ---------------------------------------------------------------------------
__global__ __launch_bounds__(256, 3) void attn_ov(const int* __restrict__ flag)
{
    const int ntb = gridDim.x - 1 - blockIdx.x;   // heavy first
    const int bh = blockIdx.y;
    const int b = bh >> 4, h = bh & 15;
    const int n0 = ntb * 128;
    const int chunks = (flag[0] != 0) ? ((n0 + 128) / JC) : (MM / JC);

    extern __shared__ __half ovs[];
    uint32_t s0 = (uint32_t)__cvta_generic_to_shared(ovs);

    const int tid = threadIdx.x;
    const int lane = tid & 31, warp = tid >> 5;
    const int g = lane >> 2, t = lane & 3;
    const int wy = warp >> 1;
    const int wx = warp & 1;

    const char* Pbytes = (const char*)(g_S16 + ((size_t)bh * NN + n0) * MM);
    const __half* Vb = g_V16 + (size_t)b * MM * DD + h * HD;

    float acc[2][4][4];
#pragma unroll
    for (int i = 0; i < 2; i++)
#pragma unroll
        for (int j = 0; j < 4; j++)
#pragma unroll
            for (int p = 0; p < 4; p++) acc[i][j][p] = 0.f;

    auto load_chunk = [&](int c, int buf) {
        const int j0 = c * JC;
#pragma unroll
        for (int i = 0; i < 4; i++) {
            int idx = tid + i * 256;            // 0..1023
            int r = idx >> 3, seg = idx & 7;
            const char* psrc = Pbytes + (size_t)r * (MM * 2) + j0 * 2 + seg * 16;
            uint32_t d = (uint32_t)(buf * OV_PS + r * PROW) * 2 + seg * 16;
            cp16(s0 + d, psrc);
        }
#pragma unroll
        for (int i = 0; i < 2; i++) {
            int idx = tid + i * 256;            // 0..511
            int r = idx >> 3, seg = idx & 7;
            size_t voff = (size_t)(j0 + r) * DD + seg * 8;
            uint32_t d = (uint32_t)(buf * OV_VS + r * VROW) * 2 + seg * 16;
            cp16(s0 + OV_OFF_VS * 2 + d, Vb + voff);
        }
    };

    load_chunk(0, 0);
    cp_commit();

    for (int c = 0; c < chunks; c++) {
        const int buf = c & 1;
        if (c + 1 < chunks) {
            load_chunk(c + 1, buf ^ 1);
            cp_commit();
            cp_wait1();
        } else {
            cp_wait0();
        }
        __syncthreads();

        const __half* PP = ovs + buf * OV_PS;
        const __half* VV = ovs + OV_OFF_VS + buf * OV_VS;

#pragma unroll
        for (int ks = 0; ks < 4; ks++) {
            const int jb = ks * 16;
            uint32_t ap[2][4];
#pragma unroll
            for (int mt = 0; mt < 2; mt++) {
                int rr = wy * 32 + mt * 16 + g;
                ap[mt][0] = *(const uint32_t*)&PP[rr * PROW + jb + 2 * t];
                ap[mt][1] = *(const uint32_t*)&PP[(rr + 8) * PROW + jb + 2 * t];
                ap[mt][2] = *(const uint32_t*)&PP[rr * PROW + jb + 8 + 2 * t];
                ap[mt][3] = *(const uint32_t*)&PP[(rr + 8) * PROW + jb + 8 + 2 * t];
            }
#pragma unroll
            for (int nt = 0; nt < 4; nt++) {
                int dd = wx * 32 + nt * 8 + g;
                uint32_t b0 = (uint32_t)*(const unsigned short*)&VV[(jb + 2 * t) * VROW + dd]
                            | ((uint32_t)*(const unsigned short*)&VV[(jb + 2 * t + 1) * VROW + dd] << 16);
                uint32_t b1 = (uint32_t)*(const unsigned short*)&VV[(jb + 8 + 2 * t) * VROW + dd]
                            | ((uint32_t)*(const unsigned short*)&VV[(jb + 9 + 2 * t) * VROW + dd] << 16);
#pragma unroll
                for (int mt = 0; mt < 2; mt++) {
                    float* d = acc[mt][nt];
                    MMA_F16(d, ap[mt][0], ap[mt][1], ap[mt][2], ap[mt][3], b0, b1);
                }
            }
        }
        __syncthreads();
    }

#pragma unroll
    for (int mt = 0; mt < 2; mt++) {
        int r0 = n0 + wy * 32 + mt * 16 + g;
        int r1 = r0 + 8;
#pragma unroll
        for (int nt = 0; nt < 4; nt++) {
            int col = h * HD + wx * 32 + nt * 8 + 2 * t;
            float* d = acc[mt][nt];
            *(float2*)&g_O[((size_t)b * NN + r0) * DD + col] = make_float2(d[0], d[1]);
            *(float2*)&g_O[((size_t)b * NN + r1) * DD + col] = make_float2(d[2], d[3]);
        }
    }
}

// ---------------------------------------------------------------------------
// Launch
// ---------------------------------------------------------------------------
extern "C" void kernel_launch(void* const* d_in, const int* in_sizes, int n_in,
                              void* d_out, int out_size)
{
    const float* query = (const float*)d_in[0];
    const float* key   = (const float*)d_in[1];
    const float* value = (const float*)d_in[2];
    const int*   kpl   = (const int*)d_in[3];
    const int*   flag  = (const int*)d_in[4];
    const float* wq_w  = (const float*)d_in[5];
    const float* wq_b  = (const float*)d_in[6];
    const float* wk_w  = (const float*)d_in[7];
    const float* wk_b  = (const float*)d_in[8];
    const float* wv_w  = (const float*)d_in[9];
    const float* wv_b  = (const float*)d_in[10];
    const float* wo_w  = (const float*)d_in[11];
    const float* wo_b  = (const float*)d_in[12];
    float* out = (float*)d_out;

    static bool attr_done = false;
    if (!attr_done) {
        cudaFuncSetAttribute(qkv_mma,    cudaFuncAttributeMaxDynamicSharedMemorySize, SMEMB);
        cudaFuncSetAttribute(proj_mma,   cudaFuncAttributeMaxDynamicSharedMemorySize, SMEMB);
        cudaFuncSetAttribute(scores_f16, cudaFuncAttributeMaxDynamicSharedMemorySize, SC_SMEMB);
        cudaFuncSetAttribute(attn_ov,    cudaFuncAttributeMaxDynamicSharedMemorySize, OV_SMEMB);
        attr_done = true;
    }

    float *Op;
    cudaGetSymbolAddress((void**)&Op, g_O);

    qkv_mma<<<dim3(32, 24), 256, SMEMB>>>(query, key, value,
                                          wq_w, wk_w, wv_w,
                                          wq_b, wk_b, wv_b, kpl);

    scores_f16<<<dim3(16, 32), 256, SC_SMEMB>>>(flag);

    const long long need = (long long)BB * NN * DD + (long long)BB * NN * MM;
    float* wout = ((long long)out_size >= need) ? (out + (size_t)BB * NN * DD)
                                                : nullptr;
    softmax_wmean<<<BB * NN, 256>>>(flag, wout);

    attn_ov<<<dim3(16, 32), 256, OV_SMEMB>>>(flag);

    proj_mma<<<dim3(32, 8), 256, SMEMB>>>(Op, wo_w, wo_b, out);
}